// round 2
// baseline (speedup 1.0000x reference)
#include <cuda_runtime.h>
#include <math.h>
#include <stdint.h>

// Problem constants (fixed by the dataset)
#define NN 100000
#define EE 400000
#define BB 512

// ---------------- scratch (no allocations allowed) ----------------
__device__ float g_degf[NN];
__device__ float g_dinv[NN];
__device__ float g_bufA[(size_t)NN * 256];   // aggregation target
__device__ float g_bufB[(size_t)NN * 256];   // post-GEMM features
__device__ float g_x2[BB * 256];             // pooled max
__device__ float g_hidden[BB * 1024];        // fc1 output

// ---------------- small kernels ----------------
__global__ void init_deg_kernel(float* degf, int n) {
    int i = blockIdx.x * blockDim.x + threadIdx.x;
    if (i < n) degf[i] = 1.0f;   // self-loop
}

__global__ void deg_scatter_kernel(const int* __restrict__ col, float* degf, int e) {
    int i = blockIdx.x * blockDim.x + threadIdx.x;
    if (i < e) atomicAdd(&degf[col[i]], 1.0f);
}

__global__ void dinv_kernel(const float* __restrict__ degf, float* dinv, int n) {
    int i = blockIdx.x * blockDim.x + threadIdx.x;
    if (i < n) dinv[i] = rsqrtf(degf[i]);
}

// agg[i] = dinv[i]^2 * h[i]  (self-loop term, also serves as the zero-init)
__global__ void selfloop_init_kernel(const float* __restrict__ h,
                                     const float* __restrict__ dinv,
                                     float* __restrict__ agg, int n, int F) {
    int fc = F >> 2;
    size_t idx = (size_t)blockIdx.x * blockDim.x + threadIdx.x;
    size_t total = (size_t)n * fc;
    if (idx >= total) return;
    int row = (int)(idx / fc);
    int c4  = (int)(idx % fc) << 2;
    float d = dinv[row];
    float s = d * d;
    float4 v = *(const float4*)&h[(size_t)row * F + c4];
    float4 o;
    o.x = s * v.x; o.y = s * v.y; o.z = s * v.z; o.w = s * v.w;
    *(float4*)&agg[(size_t)row * F + c4] = o;
}

// agg[col[e]] += dinv[row]*dinv[col] * h[row[e]]
__global__ void edge_scatter_kernel(const int* __restrict__ erow,
                                    const int* __restrict__ ecol,
                                    const float* __restrict__ dinv,
                                    const float* __restrict__ h,
                                    float* __restrict__ agg, int e, int F) {
    int fc = F >> 2;
    size_t idx = (size_t)blockIdx.x * blockDim.x + threadIdx.x;
    size_t total = (size_t)e * fc;
    if (idx >= total) return;
    int ed = (int)(idx / fc);
    int c4 = (int)(idx % fc) << 2;
    int r = __ldg(&erow[ed]);
    int c = __ldg(&ecol[ed]);
    float nrm = __ldg(&dinv[r]) * __ldg(&dinv[c]);
    float4 v = *(const float4*)&h[(size_t)r * F + c4];
    float* dst = &agg[(size_t)c * F + c4];
    atomicAdd(dst + 0, nrm * v.x);
    atomicAdd(dst + 1, nrm * v.y);
    atomicAdd(dst + 2, nrm * v.z);
    atomicAdd(dst + 3, nrm * v.w);
}

__global__ void zero_kernel(float* p, int n) {
    int i = blockIdx.x * blockDim.x + threadIdx.x;
    if (i < n) p[i] = 0.0f;
}

// ---------------- tiled SGEMM: C[Nr,K] = A[Nr,M] @ W[M,K] + bias -------------
// BM=128 BN=128 BK=16, 256 threads, 8x8 per-thread tile, double-buffered smem.
// Requires M % 16 == 0, K % 4 == 0 (true for all call sites).
// Optional fused epilogues:
//   relu      : clamp at 0
//   pool/batch: atomicMax-scatter the (relu'd) output into pool[batch[row]*K+col]
//   amvo path : amvo_out[r,c] = mu_in[r,c] + eps_in[r,c] * exp(0.5 * C[r,c])
__global__ __launch_bounds__(256) void sgemm128_kernel(
    const float* __restrict__ A, const float* __restrict__ W,
    const float* __restrict__ bias, float* __restrict__ C,
    int Nr, int M, int K, int relu,
    const float* __restrict__ mu_in, const float* __restrict__ eps_in,
    float* __restrict__ amvo_out,
    const int* __restrict__ batch, float* __restrict__ pool) {
    const int BM = 128, BN = 128, BK = 16;
    __shared__ float As[2][BK][BM + 4];
    __shared__ float Bs[2][BK][BN];
    int row0 = blockIdx.y * BM;
    int col0 = blockIdx.x * BN;
    int tid = threadIdx.x;
    int tr = (tid >> 4) << 3;   // 0..120
    int tc = (tid & 15) << 3;   // 0..120
    float acc[8][8] = {};

    auto load_stage = [&](int s, int k0) {
        // A tile: 128x16, stored transposed. 512 float4 slots, 2 per thread.
        #pragma unroll
        for (int l = tid; l < 512; l += 256) {
            int r = l >> 2;
            int m4 = (l & 3) << 2;
            float4 v = make_float4(0.f, 0.f, 0.f, 0.f);
            int gr = row0 + r;
            if (gr < Nr) v = *(const float4*)&A[(size_t)gr * M + k0 + m4];
            As[s][m4 + 0][r] = v.x;
            As[s][m4 + 1][r] = v.y;
            As[s][m4 + 2][r] = v.z;
            As[s][m4 + 3][r] = v.w;
        }
        // W tile: 16x128. 512 float4 slots, 2 per thread.
        #pragma unroll
        for (int l = tid; l < 512; l += 256) {
            int m = l >> 5;
            int c4 = (l & 31) << 2;
            float4 v = make_float4(0.f, 0.f, 0.f, 0.f);
            int gc = col0 + c4;
            if (gc < K) v = *(const float4*)&W[(size_t)(k0 + m) * K + gc];
            *(float4*)&Bs[s][m][c4] = v;
        }
    };

    load_stage(0, 0);
    __syncthreads();
    int s = 0;
    for (int k0 = 0; k0 < M; k0 += BK) {
        if (k0 + BK < M) load_stage(s ^ 1, k0 + BK);
        #pragma unroll
        for (int kk = 0; kk < BK; kk++) {
            float a[8], b[8];
            *(float4*)&a[0] = *(const float4*)&As[s][kk][tr];
            *(float4*)&a[4] = *(const float4*)&As[s][kk][tr + 4];
            *(float4*)&b[0] = *(const float4*)&Bs[s][kk][tc];
            *(float4*)&b[4] = *(const float4*)&Bs[s][kk][tc + 4];
            #pragma unroll
            for (int i = 0; i < 8; i++)
                #pragma unroll
                for (int j = 0; j < 8; j++)
                    acc[i][j] = fmaf(a[i], b[j], acc[i][j]);
        }
        __syncthreads();
        s ^= 1;
    }

    #pragma unroll
    for (int i = 0; i < 8; i++) {
        int gr = row0 + tr + i;
        if (gr >= Nr) continue;
        int bpool = (pool != nullptr) ? __ldg(&batch[gr]) : 0;
        #pragma unroll
        for (int j = 0; j < 8; j += 4) {
            int gc = col0 + tc + j;
            if (gc >= K) continue;
            float4 v;
            v.x = acc[i][j + 0] + bias[gc + 0];
            v.y = acc[i][j + 1] + bias[gc + 1];
            v.z = acc[i][j + 2] + bias[gc + 2];
            v.w = acc[i][j + 3] + bias[gc + 3];
            if (relu) {
                v.x = fmaxf(v.x, 0.f); v.y = fmaxf(v.y, 0.f);
                v.z = fmaxf(v.z, 0.f); v.w = fmaxf(v.w, 0.f);
            }
            *(float4*)&C[(size_t)gr * K + gc] = v;
            if (pool != nullptr) {
                // values are >= 0 (post-relu), so int-reinterpret max is valid
                float* p = &pool[(size_t)bpool * K + gc];
                atomicMax((int*)p + 0, __float_as_int(v.x));
                atomicMax((int*)p + 1, __float_as_int(v.y));
                atomicMax((int*)p + 2, __float_as_int(v.z));
                atomicMax((int*)p + 3, __float_as_int(v.w));
            }
            if (amvo_out != nullptr) {
                float4 m = *(const float4*)&mu_in[(size_t)gr * K + gc];
                float4 e = *(const float4*)&eps_in[(size_t)gr * K + gc];
                float4 a;
                a.x = fmaf(e.x, __expf(0.5f * v.x), m.x);
                a.y = fmaf(e.y, __expf(0.5f * v.y), m.y);
                a.z = fmaf(e.z, __expf(0.5f * v.z), m.z);
                a.w = fmaf(e.w, __expf(0.5f * v.w), m.w);
                *(float4*)&amvo_out[(size_t)gr * K + gc] = a;
            }
        }
    }
}

// ---------------- launch orchestration ----------------
static inline void run_gemm(const float* A, const float* W, const float* bias,
                            float* C, int Nr, int M, int K, int relu,
                            const float* mu_in = nullptr,
                            const float* eps_in = nullptr,
                            float* amvo_out = nullptr,
                            const int* batch = nullptr,
                            float* pool = nullptr) {
    dim3 grid((K + 127) / 128, (Nr + 127) / 128);
    sgemm128_kernel<<<grid, 256>>>(A, W, bias, C, Nr, M, K, relu,
                                   mu_in, eps_in, amvo_out, batch, pool);
}

static inline void run_aggregate(const float* h, const int* erow, const int* ecol,
                                 const float* dinv, float* agg, int F) {
    size_t sl = (size_t)NN * (F / 4);
    selfloop_init_kernel<<<(int)((sl + 255) / 256), 256>>>(h, dinv, agg, NN, F);
    size_t es = (size_t)EE * (F / 4);
    edge_scatter_kernel<<<(int)((es + 255) / 256), 256>>>(erow, ecol, dinv, h, agg, EE, F);
}

extern "C" void kernel_launch(void* const* d_in, const int* in_sizes, int n_in,
                              void* d_out, int out_size) {
    const float* x     = (const float*)d_in[0];
    const int*   ei    = (const int*)d_in[1];
    const int*   batch = (const int*)d_in[2];
    const float* eps   = (const float*)d_in[3];
    const float* W1 = (const float*)d_in[4];  const float* b1 = (const float*)d_in[5];
    const float* W2 = (const float*)d_in[6];  const float* b2 = (const float*)d_in[7];
    const float* W3 = (const float*)d_in[8];  const float* b3 = (const float*)d_in[9];
    const float* Wmu = (const float*)d_in[10]; const float* bmu = (const float*)d_in[11];
    const float* Wlv = (const float*)d_in[12]; const float* blv = (const float*)d_in[13];
    const float* fc1w = (const float*)d_in[14]; const float* fc1b = (const float*)d_in[15];
    const float* fc2w = (const float*)d_in[16]; const float* fc2b = (const float*)d_in[17];

    float* out = (float*)d_out;
    float* out_amvo = out;
    float* out_mu   = out + (size_t)NN * 256;
    float* out_lv   = out + 2 * (size_t)NN * 256;
    float* out_pmvo = out + 3 * (size_t)NN * 256;

    float *degf, *dinv, *bufA, *bufB, *x2, *hidden;
    cudaGetSymbolAddress((void**)&degf, g_degf);
    cudaGetSymbolAddress((void**)&dinv, g_dinv);
    cudaGetSymbolAddress((void**)&bufA, g_bufA);
    cudaGetSymbolAddress((void**)&bufB, g_bufB);
    cudaGetSymbolAddress((void**)&x2, g_x2);
    cudaGetSymbolAddress((void**)&hidden, g_hidden);

    const int* erow = ei;
    const int* ecol = ei + EE;

    // degree + normalization (x2 zero runs concurrently-cheap up front)
    init_deg_kernel<<<(NN + 255) / 256, 256>>>(degf, NN);
    deg_scatter_kernel<<<(EE + 255) / 256, 256>>>(ecol, degf, EE);
    dinv_kernel<<<(NN + 255) / 256, 256>>>(degf, dinv, NN);
    zero_kernel<<<(BB * 256 + 255) / 256, 256>>>(x2, BB * 256);

    // layer 1: aggregate(x,64) -> gemm 64->128 +relu
    run_aggregate(x, erow, ecol, dinv, bufA, 64);
    run_gemm(bufA, W1, b1, bufB, NN, 64, 128, 1);

    // layer 2: aggregate(h1,128) -> gemm 128->192 +relu
    run_aggregate(bufB, erow, ecol, dinv, bufA, 128);
    run_gemm(bufA, W2, b2, bufB, NN, 128, 192, 1);

    // layer 3: aggregate(h2,192) -> gemm 192->256 +relu, fused segment-max pool
    run_aggregate(bufB, erow, ecol, dinv, bufA, 192);
    run_gemm(bufA, W3, b3, bufB, NN, 192, 256, 1,
             nullptr, nullptr, nullptr, batch, x2);

    // shared aggregation for mu / logvar heads
    run_aggregate(bufB, erow, ecol, dinv, bufA, 256);
    run_gemm(bufA, Wmu, bmu, out_mu, NN, 256, 256, 0);
    // logvar GEMM with fused reparameterization epilogue (reads mu written above)
    run_gemm(bufA, Wlv, blv, out_lv, NN, 256, 256, 0,
             out_mu, eps, out_amvo);

    // MLP head on pooled features
    run_gemm(x2, fc1w, fc1b, hidden, BB, 256, 1024, 1);
    run_gemm(hidden, fc2w, fc2b, out_pmvo, BB, 1024, 128, 0);
}

// round 4
// speedup vs baseline: 1.0778x; 1.0778x over previous
#include <cuda_runtime.h>
#include <cuda_bf16.h>
#include <math.h>
#include <stdint.h>

#define NN 100000
#define EE 400000
#define BB 512

// ---------------- scratch (no allocations allowed) ----------------
__device__ float g_degf[NN];
__device__ float g_dinv[NN];
__device__ float g_bufA[(size_t)NN * 256];   // aggregation target
__device__ float g_bufB[(size_t)NN * 256];   // post-GEMM features
__device__ float g_x2[BB * 256];             // pooled max
__device__ float g_hidden[BB * 1024];        // fc1 output
__device__ __nv_bfloat16 g_wt_hi[256 * 256]; // W^T split high (bf16)
__device__ __nv_bfloat16 g_wt_lo[256 * 256]; // W^T split low  (bf16)

// ---------------- small kernels ----------------
__global__ void init_deg_kernel(float* degf, int n) {
    int i = blockIdx.x * blockDim.x + threadIdx.x;
    if (i < n) degf[i] = 1.0f;
}

__global__ void deg_scatter_kernel(const int* __restrict__ col, float* degf, int e) {
    int i = blockIdx.x * blockDim.x + threadIdx.x;
    if (i < e) atomicAdd(&degf[col[i]], 1.0f);
}

__global__ void dinv_kernel(const float* __restrict__ degf, float* dinv, int n) {
    int i = blockIdx.x * blockDim.x + threadIdx.x;
    if (i < n) dinv[i] = rsqrtf(degf[i]);
}

__global__ void selfloop_init_kernel(const float* __restrict__ h,
                                     const float* __restrict__ dinv,
                                     float* __restrict__ agg, int n, int F) {
    int fc = F >> 2;
    size_t idx = (size_t)blockIdx.x * blockDim.x + threadIdx.x;
    size_t total = (size_t)n * fc;
    if (idx >= total) return;
    int row = (int)(idx / fc);
    int c4  = (int)(idx % fc) << 2;
    float d = dinv[row];
    float s = d * d;
    float4 v = *(const float4*)&h[(size_t)row * F + c4];
    float4 o;
    o.x = s * v.x; o.y = s * v.y; o.z = s * v.z; o.w = s * v.w;
    *(float4*)&agg[(size_t)row * F + c4] = o;
}

__global__ void edge_scatter_kernel(const int* __restrict__ erow,
                                    const int* __restrict__ ecol,
                                    const float* __restrict__ dinv,
                                    const float* __restrict__ h,
                                    float* __restrict__ agg, int e, int F) {
    int fc = F >> 2;
    size_t idx = (size_t)blockIdx.x * blockDim.x + threadIdx.x;
    size_t total = (size_t)e * fc;
    if (idx >= total) return;
    int ed = (int)(idx / fc);
    int c4 = (int)(idx % fc) << 2;
    int r = __ldg(&erow[ed]);
    int c = __ldg(&ecol[ed]);
    float nrm = __ldg(&dinv[r]) * __ldg(&dinv[c]);
    float4 v = *(const float4*)&h[(size_t)r * F + c4];
    float* dst = &agg[(size_t)c * F + c4];
    atomicAdd(dst + 0, nrm * v.x);
    atomicAdd(dst + 1, nrm * v.y);
    atomicAdd(dst + 2, nrm * v.z);
    atomicAdd(dst + 3, nrm * v.w);
}

__global__ void zero_kernel(float* p, int n) {
    int i = blockIdx.x * blockDim.x + threadIdx.x;
    if (i < n) p[i] = 0.0f;
}

// ---------------- weight pre-split: W[MK,N] -> Wt_{hi,lo}[Npad,MK] bf16 -------
__global__ void wsplit_kernel(const float* __restrict__ W, int MK, int N, int Npad) {
    int idx = blockIdx.x * blockDim.x + threadIdx.x;
    if (idx >= Npad * MK) return;
    int n = idx / MK;
    int k = idx % MK;
    float v = (n < N) ? W[(size_t)k * N + n] : 0.0f;
    __nv_bfloat16 h = __float2bfloat16_rn(v);
    __nv_bfloat16 l = __float2bfloat16_rn(v - __bfloat162float(h));
    g_wt_hi[(size_t)n * MK + k] = h;
    g_wt_lo[(size_t)n * MK + k] = l;
}

// ---------------- bf16x2 tensor-core GEMM (mma.sync, generic sm_80+ PTX) ------
// C[Nr,Kout] = A[Nr,MK] @ W[MK,Kout] + bias,  A,W split into bf16 hi+lo,
// acc += Ahi*Bhi + Ahi*Blo + Alo*Bhi  (fp32 accumulators).
// CTA tile 128x128, 8 warps of 64x32, BK=32, 2-stage smem + register prefetch.
// Fused epilogues: relu, pool-max scatter, amvo reparameterization.

#define LDSM_X4(R, ADDR) \
    asm volatile("ldmatrix.sync.aligned.m8n8.x4.shared.b16 {%0,%1,%2,%3}, [%4];" \
        : "=r"((R)[0]), "=r"((R)[1]), "=r"((R)[2]), "=r"((R)[3]) : "r"(ADDR))

#define LDSM_X2(R, ADDR) \
    asm volatile("ldmatrix.sync.aligned.m8n8.x2.shared.b16 {%0,%1}, [%2];" \
        : "=r"((R)[0]), "=r"((R)[1]) : "r"(ADDR))

#define MMA_BF16(CC, AA, BB2) \
    asm volatile("mma.sync.aligned.m16n8k16.row.col.f32.bf16.bf16.f32 " \
        "{%0,%1,%2,%3}, {%4,%5,%6,%7}, {%8,%9}, {%0,%1,%2,%3};" \
        : "+f"((CC)[0]), "+f"((CC)[1]), "+f"((CC)[2]), "+f"((CC)[3]) \
        : "r"((AA)[0]), "r"((AA)[1]), "r"((AA)[2]), "r"((AA)[3]), \
          "r"((BB2)[0]), "r"((BB2)[1]))

__global__ void __launch_bounds__(256)
gemm_mma_kernel(const float* __restrict__ A, const float* __restrict__ bias,
                float* __restrict__ C, int Nr, int MK, int Kout, int relu,
                const float* __restrict__ mu_in, const float* __restrict__ eps_in,
                float* __restrict__ amvo_out,
                const int* __restrict__ batch, float* __restrict__ pool) {
    extern __shared__ char smem[];
    const int tid = threadIdx.x;
    const int w = tid >> 5, lid = tid & 31;
    const int wr = w >> 2, wc = w & 3;          // warp grid 2x4
    const int row0 = blockIdx.y * 128, col0 = blockIdx.x * 128;
    const uint32_t sbase = (uint32_t)__cvta_generic_to_shared(smem);

    // stage layout (bytes): As_hi 8K | As_lo 8K | Bs_hi 8K | Bs_lo 8K = 32K/stage
    const int STAGE = 32768;

    float acc[4][4][4] = {};

    const int lrow = tid >> 1;            // 0..127
    const int lkh  = (tid & 1) * 16;      // k-half offset (elements)
    const int nc = MK >> 5;               // chunks of 32

    float4 pa[4];
    uint4 pbh[2], pbl[2];

    auto ldg_chunk = [&](int ci) {
        const int k0 = ci << 5;
        int gr = row0 + lrow;
        if (gr < Nr) {
            const float4* p = (const float4*)(A + (size_t)gr * MK + k0 + lkh);
            pa[0] = p[0]; pa[1] = p[1]; pa[2] = p[2]; pa[3] = p[3];
        } else {
            pa[0] = pa[1] = pa[2] = pa[3] = make_float4(0.f, 0.f, 0.f, 0.f);
        }
        int n = col0 + lrow;   // padded Wt rows always valid
        const uint4* ph = (const uint4*)(g_wt_hi + (size_t)n * MK + k0 + lkh);
        pbh[0] = ph[0]; pbh[1] = ph[1];
        const uint4* pl = (const uint4*)(g_wt_lo + (size_t)n * MK + k0 + lkh);
        pbl[0] = pl[0]; pbl[1] = pl[1];
    };

    auto sts_chunk = [&](int s) {
        char* st = smem + s * STAGE;
        const float* f = (const float*)pa;   // 16 floats
        uint32_t hi[8], lo[8];
        #pragma unroll
        for (int i = 0; i < 8; i++) {
            float f0 = f[2 * i], f1 = f[2 * i + 1];
            __nv_bfloat16 h0 = __float2bfloat16_rn(f0);
            __nv_bfloat16 h1 = __float2bfloat16_rn(f1);
            __nv_bfloat16 l0 = __float2bfloat16_rn(f0 - __bfloat162float(h0));
            __nv_bfloat16 l1 = __float2bfloat16_rn(f1 - __bfloat162float(h1));
            hi[i] = (uint32_t)__bfloat16_as_ushort(h0) |
                    ((uint32_t)__bfloat16_as_ushort(h1) << 16);
            lo[i] = (uint32_t)__bfloat16_as_ushort(l0) |
                    ((uint32_t)__bfloat16_as_ushort(l1) << 16);
        }
        int off = lrow * 64 + lkh * 2;   // byte offset within 128x32 bf16 tile
        *(uint4*)(st + off)           = *(uint4*)&hi[0];
        *(uint4*)(st + off + 16)      = *(uint4*)&hi[4];
        *(uint4*)(st + 8192 + off)      = *(uint4*)&lo[0];
        *(uint4*)(st + 8192 + off + 16) = *(uint4*)&lo[4];
        *(uint4*)(st + 16384 + off)      = pbh[0];
        *(uint4*)(st + 16384 + off + 16) = pbh[1];
        *(uint4*)(st + 24576 + off)      = pbl[0];
        *(uint4*)(st + 24576 + off + 16) = pbl[1];
    };

    auto compute = [&](int s) {
        const uint32_t aHiB = sbase + s * STAGE;
        const uint32_t aLoB = aHiB + 8192;
        const uint32_t bHiB = aHiB + 16384;
        const uint32_t bLoB = aHiB + 24576;
        const int sub = lid & 7;
        const int hm = (lid >> 3) & 1;
        const int hk = (lid >> 4) & 1;
        #pragma unroll
        for (int ks = 0; ks < 2; ks++) {
            uint32_t ah[4][4], al[4][4], bh[4][2], bl[4][2];
            #pragma unroll
            for (int mt = 0; mt < 4; mt++) {
                uint32_t r = wr * 64 + mt * 16 + hm * 8 + sub;
                uint32_t off = r * 64 + ks * 32 + hk * 16;
                LDSM_X4(ah[mt], aHiB + off);
                LDSM_X4(al[mt], aLoB + off);
            }
            #pragma unroll
            for (int nt = 0; nt < 4; nt++) {
                uint32_t r = wc * 32 + nt * 8 + (lid & 7);
                uint32_t off = r * 64 + ks * 32 + ((lid >> 3) & 1) * 16;
                LDSM_X2(bh[nt], bHiB + off);
                LDSM_X2(bl[nt], bLoB + off);
            }
            #pragma unroll
            for (int mt = 0; mt < 4; mt++)
                #pragma unroll
                for (int nt = 0; nt < 4; nt++) {
                    MMA_BF16(acc[mt][nt], ah[mt], bh[nt]);
                    MMA_BF16(acc[mt][nt], ah[mt], bl[nt]);
                    MMA_BF16(acc[mt][nt], al[mt], bh[nt]);
                }
        }
    };

    // ---- pipelined mainloop: prefetch next chunk into regs during compute ----
    ldg_chunk(0);
    sts_chunk(0);
    __syncthreads();
    for (int ci = 0; ci < nc; ci++) {
        int s = ci & 1;
        if (ci + 1 < nc) ldg_chunk(ci + 1);
        compute(s);
        __syncthreads();
        if (ci + 1 < nc) {
            sts_chunk(s ^ 1);
            __syncthreads();
        }
    }

    // ---- epilogue ----
    const int g = lid >> 2, tg = lid & 3;
    auto emit = [&](int row, int col, float v0, float v1) {
        if (row >= Nr) return;
        v0 += __ldg(&bias[col]);
        v1 += __ldg(&bias[col + 1]);
        if (relu) { v0 = fmaxf(v0, 0.f); v1 = fmaxf(v1, 0.f); }
        float2 v = make_float2(v0, v1);
        *(float2*)&C[(size_t)row * Kout + col] = v;
        if (pool != nullptr) {
            int bp = __ldg(&batch[row]);
            atomicMax((int*)&pool[(size_t)bp * Kout + col],     __float_as_int(v0));
            atomicMax((int*)&pool[(size_t)bp * Kout + col + 1], __float_as_int(v1));
        }
        if (amvo_out != nullptr) {
            float2 m = *(const float2*)&mu_in[(size_t)row * Kout + col];
            float2 e = *(const float2*)&eps_in[(size_t)row * Kout + col];
            float2 a;
            a.x = fmaf(e.x, __expf(0.5f * v0), m.x);
            a.y = fmaf(e.y, __expf(0.5f * v1), m.y);
            *(float2*)&amvo_out[(size_t)row * Kout + col] = a;
        }
    };
    #pragma unroll
    for (int mt = 0; mt < 4; mt++) {
        int rowb = row0 + wr * 64 + mt * 16 + g;
        #pragma unroll
        for (int nt = 0; nt < 4; nt++) {
            int col = col0 + wc * 32 + nt * 8 + 2 * tg;
            if (col >= Kout) continue;
            emit(rowb,     col, acc[mt][nt][0], acc[mt][nt][1]);
            emit(rowb + 8, col, acc[mt][nt][2], acc[mt][nt][3]);
        }
    }
}

// ---------------- fp32 SGEMM for the tiny FC head (proven R1 kernel) ----------
__global__ __launch_bounds__(256) void sgemm_bias_kernel(
    const float* __restrict__ A, const float* __restrict__ W,
    const float* __restrict__ bias, float* __restrict__ C,
    int Nr, int M, int K, int relu) {
    const int BM = 128, BN = 64, BK = 16, TM = 8, TN = 4;
    __shared__ float As[BK][BM + 4];
    __shared__ float Bs[BK][BN];
    int row0 = blockIdx.y * BM;
    int col0 = blockIdx.x * BN;
    int tid = threadIdx.x;
    int tr = (tid / 16) * TM;
    int tc = (tid % 16) * TN;
    float acc[TM][TN] = {};

    for (int k0 = 0; k0 < M; k0 += BK) {
        #pragma unroll
        for (int l = tid; l < (BM * BK) / 4; l += 256) {
            int r = l >> 2;
            int m4 = (l & 3) << 2;
            float4 v = make_float4(0.f, 0.f, 0.f, 0.f);
            int gr = row0 + r;
            if (gr < Nr) v = *(const float4*)&A[(size_t)gr * M + k0 + m4];
            As[m4 + 0][r] = v.x;
            As[m4 + 1][r] = v.y;
            As[m4 + 2][r] = v.z;
            As[m4 + 3][r] = v.w;
        }
        {
            int m = tid >> 4;
            int c4 = (tid & 15) << 2;
            float4 v = *(const float4*)&W[(size_t)(k0 + m) * K + col0 + c4];
            *(float4*)&Bs[m][c4] = v;
        }
        __syncthreads();
        #pragma unroll
        for (int kk = 0; kk < BK; kk++) {
            float a[TM], b[TN];
            #pragma unroll
            for (int i = 0; i < TM; i++) a[i] = As[kk][tr + i];
            #pragma unroll
            for (int j = 0; j < TN; j++) b[j] = Bs[kk][tc + j];
            #pragma unroll
            for (int i = 0; i < TM; i++)
                #pragma unroll
                for (int j = 0; j < TN; j++)
                    acc[i][j] = fmaf(a[i], b[j], acc[i][j]);
        }
        __syncthreads();
    }

    #pragma unroll
    for (int i = 0; i < TM; i++) {
        int gr = row0 + tr + i;
        if (gr >= Nr) continue;
        #pragma unroll
        for (int j = 0; j < TN; j++) {
            int gc = col0 + tc + j;
            float v = acc[i][j] + bias[gc];
            if (relu) v = fmaxf(v, 0.0f);
            C[(size_t)gr * K + gc] = v;
        }
    }
}

// ---------------- launch orchestration ----------------
static inline void run_aggregate(const float* h, const int* erow, const int* ecol,
                                 const float* dinv, float* agg, int F) {
    size_t sl = (size_t)NN * (F / 4);
    selfloop_init_kernel<<<(int)((sl + 255) / 256), 256>>>(h, dinv, agg, NN, F);
    size_t es = (size_t)EE * (F / 4);
    edge_scatter_kernel<<<(int)((es + 255) / 256), 256>>>(erow, ecol, dinv, h, agg, EE, F);
}

static inline void run_gemm_mma(const float* A, const float* W, const float* bias,
                                float* C, int Nr, int MK, int Kout, int relu,
                                const float* mu_in = nullptr,
                                const float* eps_in = nullptr,
                                float* amvo_out = nullptr,
                                const int* batch = nullptr,
                                float* pool = nullptr) {
    int gx = (Kout + 127) / 128;
    int npad = gx * 128;
    int wn = npad * MK;
    wsplit_kernel<<<(wn + 255) / 256, 256>>>(W, MK, Kout, npad);
    static bool attr_set = false;
    if (!attr_set) {
        cudaFuncSetAttribute(gemm_mma_kernel,
                             cudaFuncAttributeMaxDynamicSharedMemorySize, 65536);
        attr_set = true;
    }
    dim3 grid(gx, (Nr + 127) / 128);
    gemm_mma_kernel<<<grid, 256, 65536>>>(A, bias, C, Nr, MK, Kout, relu,
                                          mu_in, eps_in, amvo_out, batch, pool);
}

extern "C" void kernel_launch(void* const* d_in, const int* in_sizes, int n_in,
                              void* d_out, int out_size) {
    const float* x     = (const float*)d_in[0];
    const int*   ei    = (const int*)d_in[1];
    const int*   batch = (const int*)d_in[2];
    const float* eps   = (const float*)d_in[3];
    const float* W1 = (const float*)d_in[4];  const float* b1 = (const float*)d_in[5];
    const float* W2 = (const float*)d_in[6];  const float* b2 = (const float*)d_in[7];
    const float* W3 = (const float*)d_in[8];  const float* b3 = (const float*)d_in[9];
    const float* Wmu = (const float*)d_in[10]; const float* bmu = (const float*)d_in[11];
    const float* Wlv = (const float*)d_in[12]; const float* blv = (const float*)d_in[13];
    const float* fc1w = (const float*)d_in[14]; const float* fc1b = (const float*)d_in[15];
    const float* fc2w = (const float*)d_in[16]; const float* fc2b = (const float*)d_in[17];

    float* out = (float*)d_out;
    float* out_amvo = out;
    float* out_mu   = out + (size_t)NN * 256;
    float* out_lv   = out + 2 * (size_t)NN * 256;
    float* out_pmvo = out + 3 * (size_t)NN * 256;

    float *degf, *dinv, *bufA, *bufB, *x2, *hidden;
    cudaGetSymbolAddress((void**)&degf, g_degf);
    cudaGetSymbolAddress((void**)&dinv, g_dinv);
    cudaGetSymbolAddress((void**)&bufA, g_bufA);
    cudaGetSymbolAddress((void**)&bufB, g_bufB);
    cudaGetSymbolAddress((void**)&x2, g_x2);
    cudaGetSymbolAddress((void**)&hidden, g_hidden);

    const int* erow = ei;
    const int* ecol = ei + EE;

    // degree + normalization, pool init
    init_deg_kernel<<<(NN + 255) / 256, 256>>>(degf, NN);
    deg_scatter_kernel<<<(EE + 255) / 256, 256>>>(ecol, degf, EE);
    dinv_kernel<<<(NN + 255) / 256, 256>>>(degf, dinv, NN);
    zero_kernel<<<(BB * 256 + 255) / 256, 256>>>(x2, BB * 256);

    // layer 1: aggregate(x,64) -> gemm 64->128 +relu
    run_aggregate(x, erow, ecol, dinv, bufA, 64);
    run_gemm_mma(bufA, W1, b1, bufB, NN, 64, 128, 1);

    // layer 2: aggregate(h1,128) -> gemm 128->192 +relu
    run_aggregate(bufB, erow, ecol, dinv, bufA, 128);
    run_gemm_mma(bufA, W2, b2, bufB, NN, 128, 192, 1);

    // layer 3: aggregate(h2,192) -> gemm 192->256 +relu, fused segment-max pool
    run_aggregate(bufB, erow, ecol, dinv, bufA, 192);
    run_gemm_mma(bufA, W3, b3, bufB, NN, 192, 256, 1,
                 nullptr, nullptr, nullptr, batch, x2);

    // shared aggregation for mu / logvar heads
    run_aggregate(bufB, erow, ecol, dinv, bufA, 256);
    run_gemm_mma(bufA, Wmu, bmu, out_mu, NN, 256, 256, 0);
    // logvar GEMM with fused reparameterization epilogue
    run_gemm_mma(bufA, Wlv, blv, out_lv, NN, 256, 256, 0,
                 out_mu, eps, out_amvo);

    // MLP head on pooled features (tiny, fp32)
    {
        dim3 g1(1024 / 64, (BB + 127) / 128);
        sgemm_bias_kernel<<<g1, 256>>>(x2, fc1w, fc1b, hidden, BB, 256, 1024, 1);
        dim3 g2(128 / 64, (BB + 127) / 128);
        sgemm_bias_kernel<<<g2, 256>>>(hidden, fc2w, fc2b, out_pmvo, BB, 1024, 128, 0);
    }
}

// round 5
// speedup vs baseline: 1.3057x; 1.2115x over previous
#include <cuda_runtime.h>
#include <cuda_bf16.h>
#include <math.h>
#include <stdint.h>

#define NN 100000
#define EE 400000
#define BB 512

// ---------------- scratch (no allocations allowed) ----------------
__device__ float g_dinv[NN];
__device__ int   g_cnt[NN];
__device__ int   g_rowptr[NN + 1];
__device__ int   g_cursor[NN];
__device__ int   g_esrc[EE];
__device__ float g_bufA[(size_t)NN * 256];   // aggregation target
__device__ float g_bufB[(size_t)NN * 256];   // post-GEMM features
__device__ float g_x2[BB * 256];             // pooled max
__device__ float g_hidden[BB * 1024];        // fc1 output
__device__ __nv_bfloat16 g_wt_hi[256 * 256]; // W^T split high (bf16)
__device__ __nv_bfloat16 g_wt_lo[256 * 256]; // W^T split low  (bf16)

// ---------------- CSR construction ----------------
__global__ void zero_int_kernel(int* p, int n) {
    int i = blockIdx.x * blockDim.x + threadIdx.x;
    if (i < n) p[i] = 0;
}

__global__ void count_kernel(const int* __restrict__ col, int* cnt, int e) {
    int i = blockIdx.x * blockDim.x + threadIdx.x;
    if (i < e) atomicAdd(&cnt[col[i]], 1);
}

__global__ void dinv_kernel(const int* __restrict__ cnt, float* dinv, int n) {
    int i = blockIdx.x * blockDim.x + threadIdx.x;
    if (i < n) dinv[i] = rsqrtf(1.0f + (float)cnt[i]);   // +1 self-loop
}

// single-block exclusive scan (shuffle-based), writes rowptr[0..n] and cursor
__global__ void scan_kernel(const int* __restrict__ cnt, int* rowptr, int* cursor, int n) {
    __shared__ int wsum[32];
    __shared__ int soff;
    const int tid = threadIdx.x;
    const int lane = tid & 31, wid = tid >> 5;
    if (tid == 0) soff = 0;
    __syncthreads();
    for (int base = 0; base < n; base += 1024) {
        int idx = base + tid;
        int v = (idx < n) ? cnt[idx] : 0;
        // warp inclusive scan
        int incl = v;
        #pragma unroll
        for (int s = 1; s < 32; s <<= 1) {
            int t = __shfl_up_sync(0xffffffff, incl, s);
            if (lane >= s) incl += t;
        }
        if (lane == 31) wsum[wid] = incl;
        __syncthreads();
        if (wid == 0) {
            int w = (lane < 32) ? wsum[lane] : 0;
            int wi = w;
            #pragma unroll
            for (int s = 1; s < 32; s <<= 1) {
                int t = __shfl_up_sync(0xffffffff, wi, s);
                if (lane >= s) wi += t;
            }
            wsum[lane] = wi - w;   // exclusive warp offsets
        }
        __syncthreads();
        int excl = incl - v + wsum[wid] + soff;
        if (idx < n) { rowptr[idx] = excl; cursor[idx] = excl; }
        __syncthreads();
        if (tid == 1023) soff += wsum[31] + incl - (incl - v) - v + 0, soff = soff; // placeholder
        __syncthreads();
        if (tid == 1023) { /* recompute correct block total below */ }
        // block total = last exclusive + last value
        if (tid == 1023) soff = excl + v;
        __syncthreads();
    }
    if (threadIdx.x == 0) rowptr[n] = soff;
}

__global__ void fill_kernel(const int* __restrict__ erow, const int* __restrict__ ecol,
                            int* cursor, int* esrc, int e) {
    int i = blockIdx.x * blockDim.x + threadIdx.x;
    if (i < e) {
        int pos = atomicAdd(&cursor[ecol[i]], 1);
        esrc[pos] = erow[i];
    }
}

// ---------------- gather-based GCN aggregation (no fp atomics) ----------------
// agg[n,c] = dinv[n] * ( dinv[n]*h[n,c] + sum_{src in CSR[n]} dinv[src]*h[src,c] )
__global__ void gather_agg_kernel(const float* __restrict__ h,
                                  const float* __restrict__ dinv,
                                  const int* __restrict__ rowptr,
                                  const int* __restrict__ esrc,
                                  float* __restrict__ agg, int n, int F) {
    int warp = (blockIdx.x * blockDim.x + threadIdx.x) >> 5;
    int lane = threadIdx.x & 31;
    int chunks = F >> 5;
    int node = warp / chunks;
    int ch = warp - node * chunks;
    if (node >= n) return;
    int c = (ch << 5) + lane;
    float dn = __ldg(&dinv[node]);
    float sum = dn * __ldg(&h[(size_t)node * F + c]);
    int s = __ldg(&rowptr[node]);
    int e = __ldg(&rowptr[node + 1]);
    int i = s;
    for (; i + 1 < e; i += 2) {
        int s0 = __ldg(&esrc[i]);
        int s1 = __ldg(&esrc[i + 1]);
        float d0 = __ldg(&dinv[s0]);
        float d1 = __ldg(&dinv[s1]);
        float h0 = __ldg(&h[(size_t)s0 * F + c]);
        float h1 = __ldg(&h[(size_t)s1 * F + c]);
        sum += d0 * h0 + d1 * h1;
    }
    if (i < e) {
        int s0 = __ldg(&esrc[i]);
        sum += __ldg(&dinv[s0]) * __ldg(&h[(size_t)s0 * F + c]);
    }
    agg[(size_t)node * F + c] = dn * sum;
}

__global__ void zero_kernel(float* p, int n) {
    int i = blockIdx.x * blockDim.x + threadIdx.x;
    if (i < n) p[i] = 0.0f;
}

// ---------------- weight pre-split: W[MK,N] -> Wt_{hi,lo}[Npad,MK] bf16 -------
__global__ void wsplit_kernel(const float* __restrict__ W, int MK, int N, int Npad) {
    int idx = blockIdx.x * blockDim.x + threadIdx.x;
    if (idx >= Npad * MK) return;
    int n = idx / MK;
    int k = idx % MK;
    float v = (n < N) ? W[(size_t)k * N + n] : 0.0f;
    __nv_bfloat16 h = __float2bfloat16_rn(v);
    __nv_bfloat16 l = __float2bfloat16_rn(v - __bfloat162float(h));
    g_wt_hi[(size_t)n * MK + k] = h;
    g_wt_lo[(size_t)n * MK + k] = l;
}

// ---------------- bf16x3 tensor-core GEMM (mma.sync) --------------------------
// Tiles stored with 80-byte row stride: (addr/16) mod 8 = (5r+c) mod 8 is a
// bijection over any 8 consecutive rows -> conflict-free ldmatrix phases.
#define RS 80

#define LDSM_X4(R, ADDR) \
    asm volatile("ldmatrix.sync.aligned.m8n8.x4.shared.b16 {%0,%1,%2,%3}, [%4];" \
        : "=r"((R)[0]), "=r"((R)[1]), "=r"((R)[2]), "=r"((R)[3]) : "r"(ADDR))

#define MMA_BF16(CC, AA, B0, B1) \
    asm volatile("mma.sync.aligned.m16n8k16.row.col.f32.bf16.bf16.f32 " \
        "{%0,%1,%2,%3}, {%4,%5,%6,%7}, {%8,%9}, {%0,%1,%2,%3};" \
        : "+f"((CC)[0]), "+f"((CC)[1]), "+f"((CC)[2]), "+f"((CC)[3]) \
        : "r"((AA)[0]), "r"((AA)[1]), "r"((AA)[2]), "r"((AA)[3]), \
          "r"(B0), "r"(B1))

__global__ void __launch_bounds__(256)
gemm_mma_kernel(const float* __restrict__ A, const float* __restrict__ bias,
                float* __restrict__ C, int Nr, int MK, int Kout, int relu,
                const float* __restrict__ mu_in, const float* __restrict__ eps_in,
                float* __restrict__ amvo_out,
                const int* __restrict__ batch, float* __restrict__ pool) {
    extern __shared__ char smem[];
    const int tid = threadIdx.x;
    const int w = tid >> 5, lid = tid & 31;
    const int wr = w >> 2, wc = w & 3;          // warp grid 2x4 over 128x128
    const int row0 = blockIdx.y * 128, col0 = blockIdx.x * 128;
    const uint32_t sbase = (uint32_t)__cvta_generic_to_shared(smem);

    const int TILE = 128 * RS;                   // 10240 B per tile
    const int STAGE = 4 * TILE;                  // AsHi | AsLo | BsHi | BsLo

    float acc[4][4][4] = {};

    const int lrow = tid >> 1;            // 0..127
    const int lk16 = (tid & 1);           // which 16-element k half this thread loads
    const int nc = MK >> 5;               // chunks of 32

    float4 pa[4];
    uint4 pbh[2], pbl[2];

    auto ldg_chunk = [&](int ci) {
        const int k0 = (ci << 5) + lk16 * 16;
        int gr = row0 + lrow;
        if (gr < Nr) {
            const float4* p = (const float4*)(A + (size_t)gr * MK + k0);
            pa[0] = p[0]; pa[1] = p[1]; pa[2] = p[2]; pa[3] = p[3];
        } else {
            pa[0] = pa[1] = pa[2] = pa[3] = make_float4(0.f, 0.f, 0.f, 0.f);
        }
        int n = col0 + lrow;   // padded Wt rows always valid
        const uint4* ph = (const uint4*)(g_wt_hi + (size_t)n * MK + k0);
        pbh[0] = ph[0]; pbh[1] = ph[1];
        const uint4* pl = (const uint4*)(g_wt_lo + (size_t)n * MK + k0);
        pbl[0] = pl[0]; pbl[1] = pl[1];
    };

    auto sts_chunk = [&](int s) {
        char* st = smem + s * STAGE;
        const float* f = (const float*)pa;   // 16 floats
        uint32_t hi[8], lo[8];
        #pragma unroll
        for (int i = 0; i < 8; i++) {
            float f0 = f[2 * i], f1 = f[2 * i + 1];
            __nv_bfloat16 h0 = __float2bfloat16_rn(f0);
            __nv_bfloat16 h1 = __float2bfloat16_rn(f1);
            __nv_bfloat16 l0 = __float2bfloat16_rn(f0 - __bfloat162float(h0));
            __nv_bfloat16 l1 = __float2bfloat16_rn(f1 - __bfloat162float(h1));
            hi[i] = (uint32_t)__bfloat16_as_ushort(h0) |
                    ((uint32_t)__bfloat16_as_ushort(h1) << 16);
            lo[i] = (uint32_t)__bfloat16_as_ushort(l0) |
                    ((uint32_t)__bfloat16_as_ushort(l1) << 16);
        }
        int off = lrow * RS + lk16 * 32;   // two 16B chunks per thread
        *(uint4*)(st + off)                 = *(uint4*)&hi[0];
        *(uint4*)(st + off + 16)            = *(uint4*)&hi[4];
        *(uint4*)(st + TILE + off)          = *(uint4*)&lo[0];
        *(uint4*)(st + TILE + off + 16)     = *(uint4*)&lo[4];
        *(uint4*)(st + 2 * TILE + off)      = pbh[0];
        *(uint4*)(st + 2 * TILE + off + 16) = pbh[1];
        *(uint4*)(st + 3 * TILE + off)      = pbl[0];
        *(uint4*)(st + 3 * TILE + off + 16) = pbl[1];
    };

    auto compute = [&](int s) {
        const uint32_t aHiB = sbase + s * STAGE;
        const uint32_t aLoB = aHiB + TILE;
        const uint32_t bHiB = aHiB + 2 * TILE;
        const uint32_t bLoB = aHiB + 3 * TILE;
        const int sub = lid & 7;
        const int g1 = (lid >> 3) & 1;   // A: m-half / B: k-half
        const int g2 = (lid >> 4) & 1;   // A: k-half / B: n-half
        #pragma unroll
        for (int ks = 0; ks < 2; ks++) {
            uint32_t ah[4][4], al[4][4], bh[2][4], bl[2][4];
            #pragma unroll
            for (int mt = 0; mt < 4; mt++) {
                uint32_t r = wr * 64 + mt * 16 + g1 * 8 + sub;
                uint32_t off = r * RS + (ks * 2 + g2) * 16;
                LDSM_X4(ah[mt], aHiB + off);
                LDSM_X4(al[mt], aLoB + off);
            }
            #pragma unroll
            for (int np = 0; np < 2; np++) {     // pairs of n-tiles
                uint32_t r = wc * 32 + np * 16 + g2 * 8 + sub;
                uint32_t off = r * RS + (ks * 2 + g1) * 16;
                LDSM_X4(bh[np], bHiB + off);
                LDSM_X4(bl[np], bLoB + off);
            }
            #pragma unroll
            for (int mt = 0; mt < 4; mt++)
                #pragma unroll
                for (int nt = 0; nt < 4; nt++) {
                    const uint32_t* BH = &bh[nt >> 1][(nt & 1) * 2];
                    const uint32_t* BL = &bl[nt >> 1][(nt & 1) * 2];
                    MMA_BF16(acc[mt][nt], ah[mt], BH[0], BH[1]);
                    MMA_BF16(acc[mt][nt], ah[mt], BL[0], BL[1]);
                    MMA_BF16(acc[mt][nt], al[mt], BH[0], BH[1]);
                }
        }
    };

    // ---- mainloop: one __syncthreads per chunk ----
    ldg_chunk(0);
    sts_chunk(0);
    __syncthreads();
    for (int ci = 0; ci < nc; ci++) {
        int s = ci & 1;
        if (ci + 1 < nc) {
            ldg_chunk(ci + 1);
            compute(s);
            sts_chunk(s ^ 1);   // writes other stage; compute(s) already done locally
        } else {
            compute(s);
        }
        __syncthreads();
    }

    // ---- epilogue ----
    const int g = lid >> 2, tg = lid & 3;
    auto emit = [&](int row, int col, float v0, float v1) {
        if (row >= Nr) return;
        v0 += __ldg(&bias[col]);
        v1 += __ldg(&bias[col + 1]);
        if (relu) { v0 = fmaxf(v0, 0.f); v1 = fmaxf(v1, 0.f); }
        float2 v = make_float2(v0, v1);
        *(float2*)&C[(size_t)row * Kout + col] = v;
        if (pool != nullptr) {
            int bp = __ldg(&batch[row]);
            atomicMax((int*)&pool[(size_t)bp * Kout + col],     __float_as_int(v0));
            atomicMax((int*)&pool[(size_t)bp * Kout + col + 1], __float_as_int(v1));
        }
        if (amvo_out != nullptr) {
            float2 m = *(const float2*)&mu_in[(size_t)row * Kout + col];
            float2 e = *(const float2*)&eps_in[(size_t)row * Kout + col];
            float2 a;
            a.x = fmaf(e.x, __expf(0.5f * v0), m.x);
            a.y = fmaf(e.y, __expf(0.5f * v1), m.y);
            *(float2*)&amvo_out[(size_t)row * Kout + col] = a;
        }
    };
    #pragma unroll
    for (int mt = 0; mt < 4; mt++) {
        int rowb = row0 + wr * 64 + mt * 16 + g;
        #pragma unroll
        for (int nt = 0; nt < 4; nt++) {
            int col = col0 + wc * 32 + nt * 8 + 2 * tg;
            if (col >= Kout) continue;
            emit(rowb,     col, acc[mt][nt][0], acc[mt][nt][1]);
            emit(rowb + 8, col, acc[mt][nt][2], acc[mt][nt][3]);
        }
    }
}

// ---------------- fp32 SGEMM for the tiny FC head ----------------
__global__ __launch_bounds__(256) void sgemm_bias_kernel(
    const float* __restrict__ A, const float* __restrict__ W,
    const float* __restrict__ bias, float* __restrict__ C,
    int Nr, int M, int K, int relu) {
    const int BM = 128, BN = 64, BK = 16, TM = 8, TN = 4;
    __shared__ float As[BK][BM + 4];
    __shared__ float Bs[BK][BN];
    int row0 = blockIdx.y * BM;
    int col0 = blockIdx.x * BN;
    int tid = threadIdx.x;
    int tr = (tid / 16) * TM;
    int tc = (tid % 16) * TN;
    float acc[TM][TN] = {};

    for (int k0 = 0; k0 < M; k0 += BK) {
        #pragma unroll
        for (int l = tid; l < (BM * BK) / 4; l += 256) {
            int r = l >> 2;
            int m4 = (l & 3) << 2;
            float4 v = make_float4(0.f, 0.f, 0.f, 0.f);
            int gr = row0 + r;
            if (gr < Nr) v = *(const float4*)&A[(size_t)gr * M + k0 + m4];
            As[m4 + 0][r] = v.x;
            As[m4 + 1][r] = v.y;
            As[m4 + 2][r] = v.z;
            As[m4 + 3][r] = v.w;
        }
        {
            int m = tid >> 4;
            int c4 = (tid & 15) << 2;
            float4 v = *(const float4*)&W[(size_t)(k0 + m) * K + col0 + c4];
            *(float4*)&Bs[m][c4] = v;
        }
        __syncthreads();
        #pragma unroll
        for (int kk = 0; kk < BK; kk++) {
            float a[TM], b[TN];
            #pragma unroll
            for (int i = 0; i < TM; i++) a[i] = As[kk][tr + i];
            #pragma unroll
            for (int j = 0; j < TN; j++) b[j] = Bs[kk][tc + j];
            #pragma unroll
            for (int i = 0; i < TM; i++)
                #pragma unroll
                for (int j = 0; j < TN; j++)
                    acc[i][j] = fmaf(a[i], b[j], acc[i][j]);
        }
        __syncthreads();
    }

    #pragma unroll
    for (int i = 0; i < TM; i++) {
        int gr = row0 + tr + i;
        if (gr >= Nr) continue;
        #pragma unroll
        for (int j = 0; j < TN; j++) {
            int gc = col0 + tc + j;
            float v = acc[i][j] + bias[gc];
            if (relu) v = fmaxf(v, 0.0f);
            C[(size_t)gr * K + gc] = v;
        }
    }
}

// ---------------- launch orchestration ----------------
static inline void run_aggregate(const float* h, const float* dinv,
                                 const int* rowptr, const int* esrc,
                                 float* agg, int F) {
    int chunks = F >> 5;
    long long warps = (long long)NN * chunks;
    int blocks = (int)((warps * 32 + 255) / 256);
    gather_agg_kernel<<<blocks, 256>>>(h, dinv, rowptr, esrc, agg, NN, F);
}

static inline void run_gemm_mma(const float* A, const float* W, const float* bias,
                                float* C, int Nr, int MK, int Kout, int relu,
                                const float* mu_in = nullptr,
                                const float* eps_in = nullptr,
                                float* amvo_out = nullptr,
                                const int* batch = nullptr,
                                float* pool = nullptr) {
    int gx = (Kout + 127) / 128;
    int npad = gx * 128;
    int wn = npad * MK;
    wsplit_kernel<<<(wn + 255) / 256, 256>>>(W, MK, Kout, npad);
    const int SMEM = 2 * 4 * 128 * RS;   // 81920
    cudaFuncSetAttribute(gemm_mma_kernel,
                         cudaFuncAttributeMaxDynamicSharedMemorySize, SMEM);
    dim3 grid(gx, (Nr + 127) / 128);
    gemm_mma_kernel<<<grid, 256, SMEM>>>(A, bias, C, Nr, MK, Kout, relu,
                                         mu_in, eps_in, amvo_out, batch, pool);
}

extern "C" void kernel_launch(void* const* d_in, const int* in_sizes, int n_in,
                              void* d_out, int out_size) {
    const float* x     = (const float*)d_in[0];
    const int*   ei    = (const int*)d_in[1];
    const int*   batch = (const int*)d_in[2];
    const float* eps   = (const float*)d_in[3];
    const float* W1 = (const float*)d_in[4];  const float* b1 = (const float*)d_in[5];
    const float* W2 = (const float*)d_in[6];  const float* b2 = (const float*)d_in[7];
    const float* W3 = (const float*)d_in[8];  const float* b3 = (const float*)d_in[9];
    const float* Wmu = (const float*)d_in[10]; const float* bmu = (const float*)d_in[11];
    const float* Wlv = (const float*)d_in[12]; const float* blv = (const float*)d_in[13];
    const float* fc1w = (const float*)d_in[14]; const float* fc1b = (const float*)d_in[15];
    const float* fc2w = (const float*)d_in[16]; const float* fc2b = (const float*)d_in[17];

    float* out = (float*)d_out;
    float* out_amvo = out;
    float* out_mu   = out + (size_t)NN * 256;
    float* out_lv   = out + 2 * (size_t)NN * 256;
    float* out_pmvo = out + 3 * (size_t)NN * 256;

    float *dinv, *bufA, *bufB, *x2, *hidden;
    int *cnt, *rowptr, *cursor, *esrc;
    cudaGetSymbolAddress((void**)&dinv, g_dinv);
    cudaGetSymbolAddress((void**)&cnt, g_cnt);
    cudaGetSymbolAddress((void**)&rowptr, g_rowptr);
    cudaGetSymbolAddress((void**)&cursor, g_cursor);
    cudaGetSymbolAddress((void**)&esrc, g_esrc);
    cudaGetSymbolAddress((void**)&bufA, g_bufA);
    cudaGetSymbolAddress((void**)&bufB, g_bufB);
    cudaGetSymbolAddress((void**)&x2, g_x2);
    cudaGetSymbolAddress((void**)&hidden, g_hidden);

    const int* erow = ei;
    const int* ecol = ei + EE;

    // CSR build + normalization + pool init
    zero_int_kernel<<<(NN + 255) / 256, 256>>>(cnt, NN);
    count_kernel<<<(EE + 255) / 256, 256>>>(ecol, cnt, EE);
    dinv_kernel<<<(NN + 255) / 256, 256>>>(cnt, dinv, NN);
    scan_kernel<<<1, 1024>>>(cnt, rowptr, cursor, NN);
    fill_kernel<<<(EE + 255) / 256, 256>>>(erow, ecol, cursor, esrc, EE);
    zero_kernel<<<(BB * 256 + 255) / 256, 256>>>(x2, BB * 256);

    // layer 1: aggregate(x,64) -> gemm 64->128 +relu
    run_aggregate(x, dinv, rowptr, esrc, bufA, 64);
    run_gemm_mma(bufA, W1, b1, bufB, NN, 64, 128, 1);

    // layer 2: aggregate(h1,128) -> gemm 128->192 +relu
    run_aggregate(bufB, dinv, rowptr, esrc, bufA, 128);
    run_gemm_mma(bufA, W2, b2, bufB, NN, 128, 192, 1);

    // layer 3: aggregate(h2,192) -> gemm 192->256 +relu, fused segment-max pool
    run_aggregate(bufB, dinv, rowptr, esrc, bufA, 192);
    run_gemm_mma(bufA, W3, b3, bufB, NN, 192, 256, 1,
                 nullptr, nullptr, nullptr, batch, x2);

    // shared aggregation for mu / logvar heads
    run_aggregate(bufB, dinv, rowptr, esrc, bufA, 256);
    run_gemm_mma(bufA, Wmu, bmu, out_mu, NN, 256, 256, 0);
    run_gemm_mma(bufA, Wlv, blv, out_lv, NN, 256, 256, 0,
                 out_mu, eps, out_amvo);

    // MLP head on pooled features (tiny, fp32)
    {
        dim3 g1(1024 / 64, (BB + 127) / 128);
        sgemm_bias_kernel<<<g1, 256>>>(x2, fc1w, fc1b, hidden, BB, 256, 1024, 1);
        dim3 g2(128 / 64, (BB + 127) / 128);
        sgemm_bias_kernel<<<g2, 256>>>(hidden, fc2w, fc2b, out_pmvo, BB, 1024, 128, 0);
    }
}

// round 6
// speedup vs baseline: 1.7077x; 1.3079x over previous
#include <cuda_runtime.h>
#include <cuda_bf16.h>
#include <math.h>
#include <stdint.h>

#define NN 100000
#define EE 400000
#define BB 512

// ---------------- scratch (no allocations allowed) ----------------
__device__ float g_dinv[NN];
__device__ int   g_cnt[NN];
__device__ int   g_rowptr[NN + 1];
__device__ int   g_cursor[NN];
__device__ int   g_esrc[EE];
__device__ int   g_bsums[128];
__device__ float g_bufA[(size_t)NN * 256];   // aggregation target
__device__ float g_bufB[(size_t)NN * 256];   // post-GEMM features
__device__ float g_x2[BB * 256];             // pooled max
__device__ float g_hidden[BB * 1024];        // fc1 output
__device__ __nv_bfloat16 g_wt_hi[256 * 256]; // W^T split high (bf16)
__device__ __nv_bfloat16 g_wt_lo[256 * 256]; // W^T split low  (bf16)

// ---------------- CSR construction ----------------
__global__ void zero_int_kernel(int* p, int n) {
    int i = blockIdx.x * blockDim.x + threadIdx.x;
    if (i < n) p[i] = 0;
}

__global__ void count_kernel(const int* __restrict__ col, int* cnt, int e) {
    int i = blockIdx.x * blockDim.x + threadIdx.x;
    if (i < e) atomicAdd(&cnt[col[i]], 1);
}

__global__ void dinv_kernel(const int* __restrict__ cnt, float* dinv, int n) {
    int i = blockIdx.x * blockDim.x + threadIdx.x;
    if (i < n) dinv[i] = rsqrtf(1.0f + (float)cnt[i]);   // +1 self-loop
}

// -- 3-phase parallel exclusive scan (blocks of 1024) --
__global__ void block_reduce_kernel(const int* __restrict__ cnt, int* bsums, int n) {
    __shared__ int wsum[32];
    int idx = blockIdx.x * 1024 + threadIdx.x;
    int lane = threadIdx.x & 31, wid = threadIdx.x >> 5;
    int v = (idx < n) ? cnt[idx] : 0;
    #pragma unroll
    for (int s = 16; s; s >>= 1) v += __shfl_down_sync(0xffffffffu, v, s);
    if (lane == 0) wsum[wid] = v;
    __syncthreads();
    if (wid == 0) {
        int t = wsum[lane];
        #pragma unroll
        for (int s = 16; s; s >>= 1) t += __shfl_down_sync(0xffffffffu, t, s);
        if (lane == 0) bsums[blockIdx.x] = t;
    }
}

__global__ void scan_bsums_kernel(int* bsums, int nb) {
    // single block, 128 threads (nb <= 128): exclusive scan in place
    __shared__ int ws[4];
    int tid = threadIdx.x;
    int lane = tid & 31, wid = tid >> 5;
    int v = (tid < nb) ? bsums[tid] : 0;
    int incl = v;
    #pragma unroll
    for (int s = 1; s < 32; s <<= 1) {
        int t = __shfl_up_sync(0xffffffffu, incl, s);
        if (lane >= s) incl += t;
    }
    if (lane == 31) ws[wid] = incl;
    __syncthreads();
    if (tid == 0) {
        int a = 0;
        #pragma unroll
        for (int i = 0; i < 4; i++) { int t = ws[i]; ws[i] = a; a += t; }
    }
    __syncthreads();
    if (tid < nb) bsums[tid] = incl - v + ws[wid];
}

__global__ void scan_final_kernel(const int* __restrict__ cnt, const int* __restrict__ boff,
                                  int* rowptr, int* cursor, int n) {
    __shared__ int wsum[32];
    int idx = blockIdx.x * 1024 + threadIdx.x;
    int lane = threadIdx.x & 31, wid = threadIdx.x >> 5;
    int v = (idx < n) ? cnt[idx] : 0;
    int incl = v;
    #pragma unroll
    for (int s = 1; s < 32; s <<= 1) {
        int t = __shfl_up_sync(0xffffffffu, incl, s);
        if (lane >= s) incl += t;
    }
    if (lane == 31) wsum[wid] = incl;
    __syncthreads();
    if (wid == 0) {
        int w = wsum[lane];
        int wi = w;
        #pragma unroll
        for (int s = 1; s < 32; s <<= 1) {
            int t = __shfl_up_sync(0xffffffffu, wi, s);
            if (lane >= s) wi += t;
        }
        wsum[lane] = wi - w;
    }
    __syncthreads();
    int excl = incl - v + wsum[wid] + __ldg(&boff[blockIdx.x]);
    if (idx < n) {
        rowptr[idx] = excl;
        cursor[idx] = excl;
        if (idx == n - 1) rowptr[n] = excl + v;
    }
}

__global__ void fill_kernel(const int* __restrict__ erow, const int* __restrict__ ecol,
                            int* cursor, int* esrc, int e) {
    int i = blockIdx.x * blockDim.x + threadIdx.x;
    if (i < e) {
        int pos = atomicAdd(&cursor[ecol[i]], 1);
        esrc[pos] = erow[i];
    }
}

// ---------------- gather-based GCN aggregation: warp-per-node full row --------
// agg[n,:] = dinv[n] * ( dinv[n]*h[n,:] + sum_{src in CSR[n]} dinv[src]*h[src,:] )
template <int COLS>   // COLS = F/32 floats per lane, contiguous
__global__ void gather_row_kernel(const float* __restrict__ h,
                                  const float* __restrict__ dinv,
                                  const int* __restrict__ rowptr,
                                  const int* __restrict__ esrc,
                                  float* __restrict__ agg, int n, int F) {
    int node = (blockIdx.x * blockDim.x + threadIdx.x) >> 5;
    int lane = threadIdx.x & 31;
    if (node >= n) return;
    const int c0 = lane * COLS;
    float dn = __ldg(&dinv[node]);
    float sum[COLS];
    {
        const float* r = h + (size_t)node * F + c0;
        #pragma unroll
        for (int j = 0; j < COLS; j++) sum[j] = dn * __ldg(&r[j]);
    }
    int s = __ldg(&rowptr[node]);
    int e = __ldg(&rowptr[node + 1]);
    int i = s;
    for (; i + 1 < e; i += 2) {
        int s0 = __ldg(&esrc[i]);
        int s1 = __ldg(&esrc[i + 1]);
        float d0 = __ldg(&dinv[s0]);
        float d1 = __ldg(&dinv[s1]);
        const float* r0 = h + (size_t)s0 * F + c0;
        const float* r1 = h + (size_t)s1 * F + c0;
        #pragma unroll
        for (int j = 0; j < COLS; j++) sum[j] += d0 * __ldg(&r0[j]);
        #pragma unroll
        for (int j = 0; j < COLS; j++) sum[j] += d1 * __ldg(&r1[j]);
    }
    if (i < e) {
        int s0 = __ldg(&esrc[i]);
        float d0 = __ldg(&dinv[s0]);
        const float* r0 = h + (size_t)s0 * F + c0;
        #pragma unroll
        for (int j = 0; j < COLS; j++) sum[j] += d0 * __ldg(&r0[j]);
    }
    float* o = agg + (size_t)node * F + c0;
    #pragma unroll
    for (int j = 0; j < COLS; j++) o[j] = dn * sum[j];
}

__global__ void zero_kernel(float* p, int n) {
    int i = blockIdx.x * blockDim.x + threadIdx.x;
    if (i < n) p[i] = 0.0f;
}

// ---------------- weight pre-split: W[MK,N] -> Wt_{hi,lo}[Npad,MK] bf16 -------
__global__ void wsplit_kernel(const float* __restrict__ W, int MK, int N, int Npad) {
    int idx = blockIdx.x * blockDim.x + threadIdx.x;
    if (idx >= Npad * MK) return;
    int n = idx / MK;
    int k = idx % MK;
    float v = (n < N) ? W[(size_t)k * N + n] : 0.0f;
    __nv_bfloat16 h = __float2bfloat16_rn(v);
    __nv_bfloat16 l = __float2bfloat16_rn(v - __bfloat162float(h));
    g_wt_hi[(size_t)n * MK + k] = h;
    g_wt_lo[(size_t)n * MK + k] = l;
}

// ---------------- bf16x3 tensor-core GEMM (mma.sync) --------------------------
// Tiles stored with 80-byte row stride: (addr/16) mod 8 = (5r+c) mod 8 is a
// bijection over any 8 consecutive rows -> conflict-free ldmatrix phases.
#define RS 80

#define LDSM_X4(R, ADDR) \
    asm volatile("ldmatrix.sync.aligned.m8n8.x4.shared.b16 {%0,%1,%2,%3}, [%4];" \
        : "=r"((R)[0]), "=r"((R)[1]), "=r"((R)[2]), "=r"((R)[3]) : "r"(ADDR))

#define MMA_BF16(CC, AA, B0, B1) \
    asm volatile("mma.sync.aligned.m16n8k16.row.col.f32.bf16.bf16.f32 " \
        "{%0,%1,%2,%3}, {%4,%5,%6,%7}, {%8,%9}, {%0,%1,%2,%3};" \
        : "+f"((CC)[0]), "+f"((CC)[1]), "+f"((CC)[2]), "+f"((CC)[3]) \
        : "r"((AA)[0]), "r"((AA)[1]), "r"((AA)[2]), "r"((AA)[3]), \
          "r"(B0), "r"(B1))

__global__ void __launch_bounds__(256)
gemm_mma_kernel(const float* __restrict__ A, const float* __restrict__ bias,
                float* __restrict__ C, int Nr, int MK, int Kout, int relu,
                const float* __restrict__ mu_in, const float* __restrict__ eps_in,
                float* __restrict__ amvo_out,
                const int* __restrict__ batch, float* __restrict__ pool) {
    extern __shared__ char smem[];
    const int tid = threadIdx.x;
    const int w = tid >> 5, lid = tid & 31;
    const int wr = w >> 2, wc = w & 3;          // warp grid 2x4 over 128x128
    const int row0 = blockIdx.y * 128, col0 = blockIdx.x * 128;
    const uint32_t sbase = (uint32_t)__cvta_generic_to_shared(smem);

    const int TILE = 128 * RS;                   // 10240 B per tile
    const int STAGE = 4 * TILE;                  // AsHi | AsLo | BsHi | BsLo

    float acc[4][4][4] = {};

    const int lrow = tid >> 1;            // 0..127
    const int lk16 = (tid & 1);           // which 16-element k half this thread loads
    const int nc = MK >> 5;               // chunks of 32

    float4 pa[4];
    uint4 pbh[2], pbl[2];

    auto ldg_chunk = [&](int ci) {
        const int k0 = (ci << 5) + lk16 * 16;
        int gr = row0 + lrow;
        if (gr < Nr) {
            const float4* p = (const float4*)(A + (size_t)gr * MK + k0);
            pa[0] = p[0]; pa[1] = p[1]; pa[2] = p[2]; pa[3] = p[3];
        } else {
            pa[0] = pa[1] = pa[2] = pa[3] = make_float4(0.f, 0.f, 0.f, 0.f);
        }
        int n = col0 + lrow;   // padded Wt rows always valid
        const uint4* ph = (const uint4*)(g_wt_hi + (size_t)n * MK + k0);
        pbh[0] = ph[0]; pbh[1] = ph[1];
        const uint4* pl = (const uint4*)(g_wt_lo + (size_t)n * MK + k0);
        pbl[0] = pl[0]; pbl[1] = pl[1];
    };

    auto sts_chunk = [&](int s) {
        char* st = smem + s * STAGE;
        const float* f = (const float*)pa;   // 16 floats
        uint32_t hi[8], lo[8];
        #pragma unroll
        for (int i = 0; i < 8; i++) {
            float f0 = f[2 * i], f1 = f[2 * i + 1];
            __nv_bfloat16 h0 = __float2bfloat16_rn(f0);
            __nv_bfloat16 h1 = __float2bfloat16_rn(f1);
            __nv_bfloat16 l0 = __float2bfloat16_rn(f0 - __bfloat162float(h0));
            __nv_bfloat16 l1 = __float2bfloat16_rn(f1 - __bfloat162float(h1));
            hi[i] = (uint32_t)__bfloat16_as_ushort(h0) |
                    ((uint32_t)__bfloat16_as_ushort(h1) << 16);
            lo[i] = (uint32_t)__bfloat16_as_ushort(l0) |
                    ((uint32_t)__bfloat16_as_ushort(l1) << 16);
        }
        int off = lrow * RS + lk16 * 32;   // two 16B chunks per thread
        *(uint4*)(st + off)                 = *(uint4*)&hi[0];
        *(uint4*)(st + off + 16)            = *(uint4*)&hi[4];
        *(uint4*)(st + TILE + off)          = *(uint4*)&lo[0];
        *(uint4*)(st + TILE + off + 16)     = *(uint4*)&lo[4];
        *(uint4*)(st + 2 * TILE + off)      = pbh[0];
        *(uint4*)(st + 2 * TILE + off + 16) = pbh[1];
        *(uint4*)(st + 3 * TILE + off)      = pbl[0];
        *(uint4*)(st + 3 * TILE + off + 16) = pbl[1];
    };

    auto compute = [&](int s) {
        const uint32_t aHiB = sbase + s * STAGE;
        const uint32_t aLoB = aHiB + TILE;
        const uint32_t bHiB = aHiB + 2 * TILE;
        const uint32_t bLoB = aHiB + 3 * TILE;
        const int sub = lid & 7;
        const int g1 = (lid >> 3) & 1;   // A: m-half / B: k-half
        const int g2 = (lid >> 4) & 1;   // A: k-half / B: n-half
        #pragma unroll
        for (int ks = 0; ks < 2; ks++) {
            uint32_t ah[4][4], al[4][4], bh[2][4], bl[2][4];
            #pragma unroll
            for (int mt = 0; mt < 4; mt++) {
                uint32_t r = wr * 64 + mt * 16 + g1 * 8 + sub;
                uint32_t off = r * RS + (ks * 2 + g2) * 16;
                LDSM_X4(ah[mt], aHiB + off);
                LDSM_X4(al[mt], aLoB + off);
            }
            #pragma unroll
            for (int np = 0; np < 2; np++) {     // pairs of n-tiles
                uint32_t r = wc * 32 + np * 16 + g2 * 8 + sub;
                uint32_t off = r * RS + (ks * 2 + g1) * 16;
                LDSM_X4(bh[np], bHiB + off);
                LDSM_X4(bl[np], bLoB + off);
            }
            #pragma unroll
            for (int mt = 0; mt < 4; mt++)
                #pragma unroll
                for (int nt = 0; nt < 4; nt++) {
                    const uint32_t* BH = &bh[nt >> 1][(nt & 1) * 2];
                    const uint32_t* BL = &bl[nt >> 1][(nt & 1) * 2];
                    MMA_BF16(acc[mt][nt], ah[mt], BH[0], BH[1]);
                    MMA_BF16(acc[mt][nt], ah[mt], BL[0], BL[1]);
                    MMA_BF16(acc[mt][nt], al[mt], BH[0], BH[1]);
                }
        }
    };

    // ---- mainloop: one __syncthreads per chunk ----
    ldg_chunk(0);
    sts_chunk(0);
    __syncthreads();
    for (int ci = 0; ci < nc; ci++) {
        int s = ci & 1;
        if (ci + 1 < nc) {
            ldg_chunk(ci + 1);
            compute(s);
            sts_chunk(s ^ 1);
        } else {
            compute(s);
        }
        __syncthreads();
    }

    // ---- epilogue ----
    const int g = lid >> 2, tg = lid & 3;
    auto emit = [&](int row, int col, float v0, float v1) {
        if (row >= Nr) return;
        v0 += __ldg(&bias[col]);
        v1 += __ldg(&bias[col + 1]);
        if (relu) { v0 = fmaxf(v0, 0.f); v1 = fmaxf(v1, 0.f); }
        float2 v = make_float2(v0, v1);
        *(float2*)&C[(size_t)row * Kout + col] = v;
        if (pool != nullptr) {
            int bp = __ldg(&batch[row]);
            atomicMax((int*)&pool[(size_t)bp * Kout + col],     __float_as_int(v0));
            atomicMax((int*)&pool[(size_t)bp * Kout + col + 1], __float_as_int(v1));
        }
        if (amvo_out != nullptr) {
            float2 m = *(const float2*)&mu_in[(size_t)row * Kout + col];
            float2 e = *(const float2*)&eps_in[(size_t)row * Kout + col];
            float2 a;
            a.x = fmaf(e.x, __expf(0.5f * v0), m.x);
            a.y = fmaf(e.y, __expf(0.5f * v1), m.y);
            *(float2*)&amvo_out[(size_t)row * Kout + col] = a;
        }
    };
    #pragma unroll
    for (int mt = 0; mt < 4; mt++) {
        int rowb = row0 + wr * 64 + mt * 16 + g;
        #pragma unroll
        for (int nt = 0; nt < 4; nt++) {
            int col = col0 + wc * 32 + nt * 8 + 2 * tg;
            if (col >= Kout) continue;
            emit(rowb,     col, acc[mt][nt][0], acc[mt][nt][1]);
            emit(rowb + 8, col, acc[mt][nt][2], acc[mt][nt][3]);
        }
    }
}

// ---------------- fp32 SGEMM for the tiny FC head ----------------
__global__ __launch_bounds__(256) void sgemm_bias_kernel(
    const float* __restrict__ A, const float* __restrict__ W,
    const float* __restrict__ bias, float* __restrict__ C,
    int Nr, int M, int K, int relu) {
    const int BM = 128, BN = 64, BK = 16, TM = 8, TN = 4;
    __shared__ float As[BK][BM + 4];
    __shared__ float Bs[BK][BN];
    int row0 = blockIdx.y * BM;
    int col0 = blockIdx.x * BN;
    int tid = threadIdx.x;
    int tr = (tid / 16) * TM;
    int tc = (tid % 16) * TN;
    float acc[TM][TN] = {};

    for (int k0 = 0; k0 < M; k0 += BK) {
        #pragma unroll
        for (int l = tid; l < (BM * BK) / 4; l += 256) {
            int r = l >> 2;
            int m4 = (l & 3) << 2;
            float4 v = make_float4(0.f, 0.f, 0.f, 0.f);
            int gr = row0 + r;
            if (gr < Nr) v = *(const float4*)&A[(size_t)gr * M + k0 + m4];
            As[m4 + 0][r] = v.x;
            As[m4 + 1][r] = v.y;
            As[m4 + 2][r] = v.z;
            As[m4 + 3][r] = v.w;
        }
        {
            int m = tid >> 4;
            int c4 = (tid & 15) << 2;
            float4 v = *(const float4*)&W[(size_t)(k0 + m) * K + col0 + c4];
            *(float4*)&Bs[m][c4] = v;
        }
        __syncthreads();
        #pragma unroll
        for (int kk = 0; kk < BK; kk++) {
            float a[TM], b[TN];
            #pragma unroll
            for (int i = 0; i < TM; i++) a[i] = As[kk][tr + i];
            #pragma unroll
            for (int j = 0; j < TN; j++) b[j] = Bs[kk][tc + j];
            #pragma unroll
            for (int i = 0; i < TM; i++)
                #pragma unroll
                for (int j = 0; j < TN; j++)
                    acc[i][j] = fmaf(a[i], b[j], acc[i][j]);
        }
        __syncthreads();
    }

    #pragma unroll
    for (int i = 0; i < TM; i++) {
        int gr = row0 + tr + i;
        if (gr >= Nr) continue;
        #pragma unroll
        for (int j = 0; j < TN; j++) {
            int gc = col0 + tc + j;
            float v = acc[i][j] + bias[gc];
            if (relu) v = fmaxf(v, 0.0f);
            C[(size_t)gr * K + gc] = v;
        }
    }
}

// ---------------- launch orchestration ----------------
static inline void run_aggregate(const float* h, const float* dinv,
                                 const int* rowptr, const int* esrc,
                                 float* agg, int F) {
    int blocks = (NN * 32 + 255) / 256;
    switch (F) {
        case 64:  gather_row_kernel<2><<<blocks, 256>>>(h, dinv, rowptr, esrc, agg, NN, F); break;
        case 128: gather_row_kernel<4><<<blocks, 256>>>(h, dinv, rowptr, esrc, agg, NN, F); break;
        case 192: gather_row_kernel<6><<<blocks, 256>>>(h, dinv, rowptr, esrc, agg, NN, F); break;
        default:  gather_row_kernel<8><<<blocks, 256>>>(h, dinv, rowptr, esrc, agg, NN, F); break;
    }
}

static inline void run_gemm_mma(const float* A, const float* W, const float* bias,
                                float* C, int Nr, int MK, int Kout, int relu,
                                const float* mu_in = nullptr,
                                const float* eps_in = nullptr,
                                float* amvo_out = nullptr,
                                const int* batch = nullptr,
                                float* pool = nullptr) {
    int gx = (Kout + 127) / 128;
    int npad = gx * 128;
    int wn = npad * MK;
    wsplit_kernel<<<(wn + 255) / 256, 256>>>(W, MK, Kout, npad);
    const int SMEM = 2 * 4 * 128 * RS;   // 81920
    cudaFuncSetAttribute(gemm_mma_kernel,
                         cudaFuncAttributeMaxDynamicSharedMemorySize, SMEM);
    dim3 grid(gx, (Nr + 127) / 128);
    gemm_mma_kernel<<<grid, 256, SMEM>>>(A, bias, C, Nr, MK, Kout, relu,
                                         mu_in, eps_in, amvo_out, batch, pool);
}

extern "C" void kernel_launch(void* const* d_in, const int* in_sizes, int n_in,
                              void* d_out, int out_size) {
    const float* x     = (const float*)d_in[0];
    const int*   ei    = (const int*)d_in[1];
    const int*   batch = (const int*)d_in[2];
    const float* eps   = (const float*)d_in[3];
    const float* W1 = (const float*)d_in[4];  const float* b1 = (const float*)d_in[5];
    const float* W2 = (const float*)d_in[6];  const float* b2 = (const float*)d_in[7];
    const float* W3 = (const float*)d_in[8];  const float* b3 = (const float*)d_in[9];
    const float* Wmu = (const float*)d_in[10]; const float* bmu = (const float*)d_in[11];
    const float* Wlv = (const float*)d_in[12]; const float* blv = (const float*)d_in[13];
    const float* fc1w = (const float*)d_in[14]; const float* fc1b = (const float*)d_in[15];
    const float* fc2w = (const float*)d_in[16]; const float* fc2b = (const float*)d_in[17];

    float* out = (float*)d_out;
    float* out_amvo = out;
    float* out_mu   = out + (size_t)NN * 256;
    float* out_lv   = out + 2 * (size_t)NN * 256;
    float* out_pmvo = out + 3 * (size_t)NN * 256;

    float *dinv, *bufA, *bufB, *x2, *hidden;
    int *cnt, *rowptr, *cursor, *esrc, *bsums;
    cudaGetSymbolAddress((void**)&dinv, g_dinv);
    cudaGetSymbolAddress((void**)&cnt, g_cnt);
    cudaGetSymbolAddress((void**)&rowptr, g_rowptr);
    cudaGetSymbolAddress((void**)&cursor, g_cursor);
    cudaGetSymbolAddress((void**)&esrc, g_esrc);
    cudaGetSymbolAddress((void**)&bsums, g_bsums);
    cudaGetSymbolAddress((void**)&bufA, g_bufA);
    cudaGetSymbolAddress((void**)&bufB, g_bufB);
    cudaGetSymbolAddress((void**)&x2, g_x2);
    cudaGetSymbolAddress((void**)&hidden, g_hidden);

    const int* erow = ei;
    const int* ecol = ei + EE;

    const int SCAN_BLOCKS = (NN + 1023) / 1024;   // 98

    // CSR build + normalization + pool init
    zero_int_kernel<<<(NN + 255) / 256, 256>>>(cnt, NN);
    count_kernel<<<(EE + 255) / 256, 256>>>(ecol, cnt, EE);
    dinv_kernel<<<(NN + 255) / 256, 256>>>(cnt, dinv, NN);
    block_reduce_kernel<<<SCAN_BLOCKS, 1024>>>(cnt, bsums, NN);
    scan_bsums_kernel<<<1, 128>>>(bsums, SCAN_BLOCKS);
    scan_final_kernel<<<SCAN_BLOCKS, 1024>>>(cnt, bsums, rowptr, cursor, NN);
    fill_kernel<<<(EE + 255) / 256, 256>>>(erow, ecol, cursor, esrc, EE);
    zero_kernel<<<(BB * 256 + 255) / 256, 256>>>(x2, BB * 256);

    // layer 1: aggregate(x,64) -> gemm 64->128 +relu
    run_aggregate(x, dinv, rowptr, esrc, bufA, 64);
    run_gemm_mma(bufA, W1, b1, bufB, NN, 64, 128, 1);

    // layer 2: aggregate(h1,128) -> gemm 128->192 +relu
    run_aggregate(bufB, dinv, rowptr, esrc, bufA, 128);
    run_gemm_mma(bufA, W2, b2, bufB, NN, 128, 192, 1);

    // layer 3: aggregate(h2,192) -> gemm 192->256 +relu, fused segment-max pool
    run_aggregate(bufB, dinv, rowptr, esrc, bufA, 192);
    run_gemm_mma(bufA, W3, b3, bufB, NN, 192, 256, 1,
                 nullptr, nullptr, nullptr, batch, x2);

    // shared aggregation for mu / logvar heads
    run_aggregate(bufB, dinv, rowptr, esrc, bufA, 256);
    run_gemm_mma(bufA, Wmu, bmu, out_mu, NN, 256, 256, 0);
    run_gemm_mma(bufA, Wlv, blv, out_lv, NN, 256, 256, 0,
                 out_mu, eps, out_amvo);

    // MLP head on pooled features (tiny, fp32)
    {
        dim3 g1(1024 / 64, (BB + 127) / 128);
        sgemm_bias_kernel<<<g1, 256>>>(x2, fc1w, fc1b, hidden, BB, 256, 1024, 1);
        dim3 g2(128 / 64, (BB + 127) / 128);
        sgemm_bias_kernel<<<g2, 256>>>(hidden, fc2w, fc2b, out_pmvo, BB, 1024, 128, 0);
    }
}

// round 7
// speedup vs baseline: 2.0453x; 1.1977x over previous
#include <cuda_runtime.h>
#include <cuda_bf16.h>
#include <math.h>
#include <stdint.h>

#define NN 100000
#define EE 400000
#define BB 512

// ---------------- scratch (no allocations allowed) ----------------
__device__ float g_dinv[NN];
__device__ int   g_cnt[NN];
__device__ int   g_rowptr[NN + 1];
__device__ int   g_cursor[NN];
__device__ int   g_esrc[EE];
__device__ int   g_bsums[128];
__device__ __nv_bfloat16 g_aggHi[(size_t)NN * 256];  // aggregated A, high bf16
__device__ __nv_bfloat16 g_aggLo[(size_t)NN * 256];  // aggregated A, low  bf16
__device__ float g_bufB[(size_t)NN * 256];           // post-GEMM features (fp32)
__device__ float g_x2[BB * 256];                     // pooled max
__device__ float g_hidden[BB * 1024];                // fc1 output
__device__ __nv_bfloat16 g_wt_hi[256 * 256];         // W^T split high (bf16)
__device__ __nv_bfloat16 g_wt_lo[256 * 256];         // W^T split low  (bf16)

// ---------------- CSR construction ----------------
__global__ void zero_int_kernel(int* p, int n) {
    int i = blockIdx.x * blockDim.x + threadIdx.x;
    if (i < n) p[i] = 0;
}

__global__ void count_kernel(const int* __restrict__ col, int* cnt, int e) {
    int i = blockIdx.x * blockDim.x + threadIdx.x;
    if (i < e) atomicAdd(&cnt[col[i]], 1);
}

__global__ void dinv_kernel(const int* __restrict__ cnt, float* dinv, int n) {
    int i = blockIdx.x * blockDim.x + threadIdx.x;
    if (i < n) dinv[i] = rsqrtf(1.0f + (float)cnt[i]);   // +1 self-loop
}

__global__ void block_reduce_kernel(const int* __restrict__ cnt, int* bsums, int n) {
    __shared__ int wsum[32];
    int idx = blockIdx.x * 1024 + threadIdx.x;
    int lane = threadIdx.x & 31, wid = threadIdx.x >> 5;
    int v = (idx < n) ? cnt[idx] : 0;
    #pragma unroll
    for (int s = 16; s; s >>= 1) v += __shfl_down_sync(0xffffffffu, v, s);
    if (lane == 0) wsum[wid] = v;
    __syncthreads();
    if (wid == 0) {
        int t = wsum[lane];
        #pragma unroll
        for (int s = 16; s; s >>= 1) t += __shfl_down_sync(0xffffffffu, t, s);
        if (lane == 0) bsums[blockIdx.x] = t;
    }
}

__global__ void scan_bsums_kernel(int* bsums, int nb) {
    __shared__ int ws[4];
    int tid = threadIdx.x;
    int lane = tid & 31, wid = tid >> 5;
    int v = (tid < nb) ? bsums[tid] : 0;
    int incl = v;
    #pragma unroll
    for (int s = 1; s < 32; s <<= 1) {
        int t = __shfl_up_sync(0xffffffffu, incl, s);
        if (lane >= s) incl += t;
    }
    if (lane == 31) ws[wid] = incl;
    __syncthreads();
    if (tid == 0) {
        int a = 0;
        #pragma unroll
        for (int i = 0; i < 4; i++) { int t = ws[i]; ws[i] = a; a += t; }
    }
    __syncthreads();
    if (tid < nb) bsums[tid] = incl - v + ws[wid];
}

__global__ void scan_final_kernel(const int* __restrict__ cnt, const int* __restrict__ boff,
                                  int* rowptr, int* cursor, int n) {
    __shared__ int wsum[32];
    int idx = blockIdx.x * 1024 + threadIdx.x;
    int lane = threadIdx.x & 31, wid = threadIdx.x >> 5;
    int v = (idx < n) ? cnt[idx] : 0;
    int incl = v;
    #pragma unroll
    for (int s = 1; s < 32; s <<= 1) {
        int t = __shfl_up_sync(0xffffffffu, incl, s);
        if (lane >= s) incl += t;
    }
    if (lane == 31) wsum[wid] = incl;
    __syncthreads();
    if (wid == 0) {
        int w = wsum[lane];
        int wi = w;
        #pragma unroll
        for (int s = 1; s < 32; s <<= 1) {
            int t = __shfl_up_sync(0xffffffffu, wi, s);
            if (lane >= s) wi += t;
        }
        wsum[lane] = wi - w;
    }
    __syncthreads();
    int excl = incl - v + wsum[wid] + __ldg(&boff[blockIdx.x]);
    if (idx < n) {
        rowptr[idx] = excl;
        cursor[idx] = excl;
        if (idx == n - 1) rowptr[n] = excl + v;
    }
}

__global__ void fill_kernel(const int* __restrict__ erow, const int* __restrict__ ecol,
                            int* cursor, int* esrc, int e) {
    int i = blockIdx.x * blockDim.x + threadIdx.x;
    if (i < e) {
        int pos = atomicAdd(&cursor[ecol[i]], 1);
        esrc[pos] = erow[i];
    }
}

// ---------------- gather aggregation: warp-per-node, bf16 hi/lo output --------
template <int COLS>   // COLS = F/32 floats per lane
__global__ void gather_row_kernel(const float* __restrict__ h,
                                  const float* __restrict__ dinv,
                                  const int* __restrict__ rowptr,
                                  const int* __restrict__ esrc,
                                  __nv_bfloat16* __restrict__ aggHi,
                                  __nv_bfloat16* __restrict__ aggLo,
                                  int n, int F) {
    int node = (blockIdx.x * blockDim.x + threadIdx.x) >> 5;
    int lane = threadIdx.x & 31;
    if (node >= n) return;
    const int c0 = lane * COLS;
    float dn = __ldg(&dinv[node]);
    float sum[COLS];
    {
        const float* r = h + (size_t)node * F + c0;
        #pragma unroll
        for (int j = 0; j < COLS; j++) sum[j] = dn * __ldg(&r[j]);
    }
    int s = __ldg(&rowptr[node]);
    int e = __ldg(&rowptr[node + 1]);
    int i = s;
    for (; i + 1 < e; i += 2) {
        int s0 = __ldg(&esrc[i]);
        int s1 = __ldg(&esrc[i + 1]);
        float d0 = __ldg(&dinv[s0]);
        float d1 = __ldg(&dinv[s1]);
        const float* r0 = h + (size_t)s0 * F + c0;
        const float* r1 = h + (size_t)s1 * F + c0;
        #pragma unroll
        for (int j = 0; j < COLS; j++) sum[j] += d0 * __ldg(&r0[j]);
        #pragma unroll
        for (int j = 0; j < COLS; j++) sum[j] += d1 * __ldg(&r1[j]);
    }
    if (i < e) {
        int s0 = __ldg(&esrc[i]);
        float d0 = __ldg(&dinv[s0]);
        const float* r0 = h + (size_t)s0 * F + c0;
        #pragma unroll
        for (int j = 0; j < COLS; j++) sum[j] += d0 * __ldg(&r0[j]);
    }
    __nv_bfloat16* oh = aggHi + (size_t)node * F + c0;
    __nv_bfloat16* ol = aggLo + (size_t)node * F + c0;
    #pragma unroll
    for (int j = 0; j < COLS; j++) {
        float v = dn * sum[j];
        __nv_bfloat16 hb = __float2bfloat16_rn(v);
        oh[j] = hb;
        ol[j] = __float2bfloat16_rn(v - __bfloat162float(hb));
    }
}

// layer-1 uses x directly; same kernel works (h = x, F = 64)

__global__ void zero_kernel(float* p, int n) {
    int i = blockIdx.x * blockDim.x + threadIdx.x;
    if (i < n) p[i] = 0.0f;
}

// ---------------- weight pre-split: W[MK,N] -> Wt_{hi,lo}[Npad,MK] bf16 -------
__global__ void wsplit_kernel(const float* __restrict__ W, int MK, int N, int Npad) {
    int idx = blockIdx.x * blockDim.x + threadIdx.x;
    if (idx >= Npad * MK) return;
    int n = idx / MK;
    int k = idx % MK;
    float v = (n < N) ? W[(size_t)k * N + n] : 0.0f;
    __nv_bfloat16 h = __float2bfloat16_rn(v);
    __nv_bfloat16 l = __float2bfloat16_rn(v - __bfloat162float(h));
    g_wt_hi[(size_t)n * MK + k] = h;
    g_wt_lo[(size_t)n * MK + k] = l;
}

// ---------------- bf16x3 tensor-core GEMM with cp.async -----------------------
// Tiles stored with 80-byte row stride: (addr/16) mod 8 = (5r+c) mod 8 bijective
// over 8 consecutive rows -> conflict-free ldmatrix. 16B-aligned (80 = 5*16).
#define RS 80

#define LDSM_X4(R, ADDR) \
    asm volatile("ldmatrix.sync.aligned.m8n8.x4.shared.b16 {%0,%1,%2,%3}, [%4];" \
        : "=r"((R)[0]), "=r"((R)[1]), "=r"((R)[2]), "=r"((R)[3]) : "r"(ADDR))

#define MMA_BF16(CC, AA, B0, B1) \
    asm volatile("mma.sync.aligned.m16n8k16.row.col.f32.bf16.bf16.f32 " \
        "{%0,%1,%2,%3}, {%4,%5,%6,%7}, {%8,%9}, {%0,%1,%2,%3};" \
        : "+f"((CC)[0]), "+f"((CC)[1]), "+f"((CC)[2]), "+f"((CC)[3]) \
        : "r"((AA)[0]), "r"((AA)[1]), "r"((AA)[2]), "r"((AA)[3]), \
          "r"(B0), "r"(B1))

#define CP16(DST, SRC, SZ) \
    asm volatile("cp.async.ca.shared.global [%0], [%1], 16, %2;" \
        :: "r"(DST), "l"(SRC), "r"(SZ) : "memory")

__global__ void __launch_bounds__(256)
gemm_mma_kernel(const __nv_bfloat16* __restrict__ aHi,
                const __nv_bfloat16* __restrict__ aLo,
                const float* __restrict__ bias,
                float* __restrict__ C, int Nr, int MK, int Kout, int relu,
                const float* __restrict__ mu_in, const float* __restrict__ eps_in,
                float* __restrict__ amvo_out,
                const int* __restrict__ batch, float* __restrict__ pool) {
    extern __shared__ char smem[];
    const int tid = threadIdx.x;
    const int w = tid >> 5, lid = tid & 31;
    const int wr = w >> 2, wc = w & 3;          // warp grid 2x4 over 128x128
    const int row0 = blockIdx.y * 128, col0 = blockIdx.x * 128;
    const uint32_t sbase = (uint32_t)__cvta_generic_to_shared(smem);

    const int TILE = 128 * RS;                   // 10240 B per plane
    const int STAGE = 4 * TILE;                  // AsHi | AsLo | BsHi | BsLo

    float acc[4][4][4] = {};

    const int nc = MK >> 5;               // chunks of 32

    // loader mapping: thread -> (row, 32B half of the 64B row)
    const int lr = tid >> 1;              // 0..127
    const int lhalf = tid & 1;            // 0 or 1 (32 bytes each)

    auto issue_chunk = [&](int ci, int s) {
        const int k0 = ci << 5;
        const uint32_t st = sbase + s * STAGE;
        const uint32_t dstA = st + lr * RS + lhalf * 32;
        int gr = row0 + lr;
        int sz = (gr < Nr) ? 16 : 0;
        const __nv_bfloat16* sh = aHi + (size_t)(gr < Nr ? gr : 0) * MK + k0 + lhalf * 16;
        const __nv_bfloat16* sl = aLo + (size_t)(gr < Nr ? gr : 0) * MK + k0 + lhalf * 16;
        CP16(dstA,              sh,     sz);
        CP16(dstA + 16,         sh + 8, sz);
        CP16(dstA + TILE,       sl,     sz);
        CP16(dstA + TILE + 16,  sl + 8, sz);
        int n = col0 + lr;   // padded rows always valid
        const __nv_bfloat16* bh = g_wt_hi + (size_t)n * MK + k0 + lhalf * 16;
        const __nv_bfloat16* bl = g_wt_lo + (size_t)n * MK + k0 + lhalf * 16;
        const uint32_t dstB = st + 2 * TILE + lr * RS + lhalf * 32;
        CP16(dstB,              bh,     16);
        CP16(dstB + 16,         bh + 8, 16);
        CP16(dstB + TILE,       bl,     16);
        CP16(dstB + TILE + 16,  bl + 8, 16);
        asm volatile("cp.async.commit_group;" ::: "memory");
    };

    auto compute = [&](int s) {
        const uint32_t aHiB = sbase + s * STAGE;
        const uint32_t aLoB = aHiB + TILE;
        const uint32_t bHiB = aHiB + 2 * TILE;
        const uint32_t bLoB = aHiB + 3 * TILE;
        const int sub = lid & 7;
        const int g1 = (lid >> 3) & 1;
        const int g2 = (lid >> 4) & 1;
        #pragma unroll
        for (int ks = 0; ks < 2; ks++) {
            uint32_t bh[2][4], bl[2][4];
            #pragma unroll
            for (int np = 0; np < 2; np++) {
                uint32_t r = wc * 32 + np * 16 + g2 * 8 + sub;
                uint32_t off = r * RS + (ks * 2 + g1) * 16;
                LDSM_X4(bh[np], bHiB + off);
                LDSM_X4(bl[np], bLoB + off);
            }
            {
                uint32_t af[4][4];
                #pragma unroll
                for (int mt = 0; mt < 4; mt++) {
                    uint32_t r = wr * 64 + mt * 16 + g1 * 8 + sub;
                    uint32_t off = r * RS + (ks * 2 + g2) * 16;
                    LDSM_X4(af[mt], aHiB + off);
                }
                #pragma unroll
                for (int mt = 0; mt < 4; mt++)
                    #pragma unroll
                    for (int nt = 0; nt < 4; nt++) {
                        const uint32_t* BH = &bh[nt >> 1][(nt & 1) * 2];
                        const uint32_t* BL = &bl[nt >> 1][(nt & 1) * 2];
                        MMA_BF16(acc[mt][nt], af[mt], BH[0], BH[1]);
                        MMA_BF16(acc[mt][nt], af[mt], BL[0], BL[1]);
                    }
                #pragma unroll
                for (int mt = 0; mt < 4; mt++) {
                    uint32_t r = wr * 64 + mt * 16 + g1 * 8 + sub;
                    uint32_t off = r * RS + (ks * 2 + g2) * 16;
                    LDSM_X4(af[mt], aLoB + off);
                }
                #pragma unroll
                for (int mt = 0; mt < 4; mt++)
                    #pragma unroll
                    for (int nt = 0; nt < 4; nt++) {
                        const uint32_t* BH = &bh[nt >> 1][(nt & 1) * 2];
                        MMA_BF16(acc[mt][nt], af[mt], BH[0], BH[1]);
                    }
            }
        }
    };

    // ---- mainloop: 2-stage cp.async pipeline ----
    issue_chunk(0, 0);
    if (nc > 1) issue_chunk(1, 1);
    for (int ci = 0; ci < nc; ci++) {
        int s = ci & 1;
        if (ci < nc - 1) {
            asm volatile("cp.async.wait_group 1;" ::: "memory");
        } else {
            asm volatile("cp.async.wait_group 0;" ::: "memory");
        }
        __syncthreads();
        compute(s);
        __syncthreads();
        if (ci + 2 < nc) issue_chunk(ci + 2, s);
    }

    // ---- epilogue ----
    const int g = lid >> 2, tg = lid & 3;
    auto emit = [&](int row, int col, float v0, float v1) {
        if (row >= Nr) return;
        v0 += __ldg(&bias[col]);
        v1 += __ldg(&bias[col + 1]);
        if (relu) { v0 = fmaxf(v0, 0.f); v1 = fmaxf(v1, 0.f); }
        float2 v = make_float2(v0, v1);
        *(float2*)&C[(size_t)row * Kout + col] = v;
        if (pool != nullptr) {
            int bp = __ldg(&batch[row]);
            atomicMax((int*)&pool[(size_t)bp * Kout + col],     __float_as_int(v0));
            atomicMax((int*)&pool[(size_t)bp * Kout + col + 1], __float_as_int(v1));
        }
        if (amvo_out != nullptr) {
            float2 m = *(const float2*)&mu_in[(size_t)row * Kout + col];
            float2 e = *(const float2*)&eps_in[(size_t)row * Kout + col];
            float2 a;
            a.x = fmaf(e.x, __expf(0.5f * v0), m.x);
            a.y = fmaf(e.y, __expf(0.5f * v1), m.y);
            *(float2*)&amvo_out[(size_t)row * Kout + col] = a;
        }
    };
    #pragma unroll
    for (int mt = 0; mt < 4; mt++) {
        int rowb = row0 + wr * 64 + mt * 16 + g;
        #pragma unroll
        for (int nt = 0; nt < 4; nt++) {
            int col = col0 + wc * 32 + nt * 8 + 2 * tg;
            if (col >= Kout) continue;
            emit(rowb,     col, acc[mt][nt][0], acc[mt][nt][1]);
            emit(rowb + 8, col, acc[mt][nt][2], acc[mt][nt][3]);
        }
    }
}

// ---------------- fp32 SGEMM for the tiny FC head ----------------
__global__ __launch_bounds__(256) void sgemm_bias_kernel(
    const float* __restrict__ A, const float* __restrict__ W,
    const float* __restrict__ bias, float* __restrict__ C,
    int Nr, int M, int K, int relu) {
    const int BM = 128, BN = 64, BK = 16, TM = 8, TN = 4;
    __shared__ float As[BK][BM + 4];
    __shared__ float Bs[BK][BN];
    int row0 = blockIdx.y * BM;
    int col0 = blockIdx.x * BN;
    int tid = threadIdx.x;
    int tr = (tid / 16) * TM;
    int tc = (tid % 16) * TN;
    float acc[TM][TN] = {};

    for (int k0 = 0; k0 < M; k0 += BK) {
        #pragma unroll
        for (int l = tid; l < (BM * BK) / 4; l += 256) {
            int r = l >> 2;
            int m4 = (l & 3) << 2;
            float4 v = make_float4(0.f, 0.f, 0.f, 0.f);
            int gr = row0 + r;
            if (gr < Nr) v = *(const float4*)&A[(size_t)gr * M + k0 + m4];
            As[m4 + 0][r] = v.x;
            As[m4 + 1][r] = v.y;
            As[m4 + 2][r] = v.z;
            As[m4 + 3][r] = v.w;
        }
        {
            int m = tid >> 4;
            int c4 = (tid & 15) << 2;
            float4 v = *(const float4*)&W[(size_t)(k0 + m) * K + col0 + c4];
            *(float4*)&Bs[m][c4] = v;
        }
        __syncthreads();
        #pragma unroll
        for (int kk = 0; kk < BK; kk++) {
            float a[TM], b[TN];
            #pragma unroll
            for (int i = 0; i < TM; i++) a[i] = As[kk][tr + i];
            #pragma unroll
            for (int j = 0; j < TN; j++) b[j] = Bs[kk][tc + j];
            #pragma unroll
            for (int i = 0; i < TM; i++)
                #pragma unroll
                for (int j = 0; j < TN; j++)
                    acc[i][j] = fmaf(a[i], b[j], acc[i][j]);
        }
        __syncthreads();
    }

    #pragma unroll
    for (int i = 0; i < TM; i++) {
        int gr = row0 + tr + i;
        if (gr >= Nr) continue;
        #pragma unroll
        for (int j = 0; j < TN; j++) {
            int gc = col0 + tc + j;
            float v = acc[i][j] + bias[gc];
            if (relu) v = fmaxf(v, 0.0f);
            C[(size_t)gr * K + gc] = v;
        }
    }
}

// ---------------- launch orchestration ----------------
static inline void run_aggregate(const float* h, const float* dinv,
                                 const int* rowptr, const int* esrc,
                                 __nv_bfloat16* aggHi, __nv_bfloat16* aggLo, int F) {
    int blocks = (NN * 32 + 255) / 256;
    switch (F) {
        case 64:  gather_row_kernel<2><<<blocks, 256>>>(h, dinv, rowptr, esrc, aggHi, aggLo, NN, F); break;
        case 128: gather_row_kernel<4><<<blocks, 256>>>(h, dinv, rowptr, esrc, aggHi, aggLo, NN, F); break;
        case 192: gather_row_kernel<6><<<blocks, 256>>>(h, dinv, rowptr, esrc, aggHi, aggLo, NN, F); break;
        default:  gather_row_kernel<8><<<blocks, 256>>>(h, dinv, rowptr, esrc, aggHi, aggLo, NN, F); break;
    }
}

static inline void run_gemm_mma(const __nv_bfloat16* aHi, const __nv_bfloat16* aLo,
                                const float* W, const float* bias,
                                float* C, int Nr, int MK, int Kout, int relu,
                                const float* mu_in = nullptr,
                                const float* eps_in = nullptr,
                                float* amvo_out = nullptr,
                                const int* batch = nullptr,
                                float* pool = nullptr) {
    int gx = (Kout + 127) / 128;
    int npad = gx * 128;
    int wn = npad * MK;
    wsplit_kernel<<<(wn + 255) / 256, 256>>>(W, MK, Kout, npad);
    const int SMEM = 2 * 4 * 128 * RS;   // 81920
    cudaFuncSetAttribute(gemm_mma_kernel,
                         cudaFuncAttributeMaxDynamicSharedMemorySize, SMEM);
    dim3 grid(gx, (Nr + 127) / 128);
    gemm_mma_kernel<<<grid, 256, SMEM>>>(aHi, aLo, bias, C, Nr, MK, Kout, relu,
                                         mu_in, eps_in, amvo_out, batch, pool);
}

extern "C" void kernel_launch(void* const* d_in, const int* in_sizes, int n_in,
                              void* d_out, int out_size) {
    const float* x     = (const float*)d_in[0];
    const int*   ei    = (const int*)d_in[1];
    const int*   batch = (const int*)d_in[2];
    const float* eps   = (const float*)d_in[3];
    const float* W1 = (const float*)d_in[4];  const float* b1 = (const float*)d_in[5];
    const float* W2 = (const float*)d_in[6];  const float* b2 = (const float*)d_in[7];
    const float* W3 = (const float*)d_in[8];  const float* b3 = (const float*)d_in[9];
    const float* Wmu = (const float*)d_in[10]; const float* bmu = (const float*)d_in[11];
    const float* Wlv = (const float*)d_in[12]; const float* blv = (const float*)d_in[13];
    const float* fc1w = (const float*)d_in[14]; const float* fc1b = (const float*)d_in[15];
    const float* fc2w = (const float*)d_in[16]; const float* fc2b = (const float*)d_in[17];

    float* out = (float*)d_out;
    float* out_amvo = out;
    float* out_mu   = out + (size_t)NN * 256;
    float* out_lv   = out + 2 * (size_t)NN * 256;
    float* out_pmvo = out + 3 * (size_t)NN * 256;

    float *dinv, *bufB, *x2, *hidden;
    int *cnt, *rowptr, *cursor, *esrc, *bsums;
    __nv_bfloat16 *aggHi, *aggLo;
    cudaGetSymbolAddress((void**)&dinv, g_dinv);
    cudaGetSymbolAddress((void**)&cnt, g_cnt);
    cudaGetSymbolAddress((void**)&rowptr, g_rowptr);
    cudaGetSymbolAddress((void**)&cursor, g_cursor);
    cudaGetSymbolAddress((void**)&esrc, g_esrc);
    cudaGetSymbolAddress((void**)&bsums, g_bsums);
    cudaGetSymbolAddress((void**)&aggHi, g_aggHi);
    cudaGetSymbolAddress((void**)&aggLo, g_aggLo);
    cudaGetSymbolAddress((void**)&bufB, g_bufB);
    cudaGetSymbolAddress((void**)&x2, g_x2);
    cudaGetSymbolAddress((void**)&hidden, g_hidden);

    const int* erow = ei;
    const int* ecol = ei + EE;

    const int SCAN_BLOCKS = (NN + 1023) / 1024;   // 98

    // CSR build + normalization + pool init
    zero_int_kernel<<<(NN + 255) / 256, 256>>>(cnt, NN);
    count_kernel<<<(EE + 255) / 256, 256>>>(ecol, cnt, EE);
    dinv_kernel<<<(NN + 255) / 256, 256>>>(cnt, dinv, NN);
    block_reduce_kernel<<<SCAN_BLOCKS, 1024>>>(cnt, bsums, NN);
    scan_bsums_kernel<<<1, 128>>>(bsums, SCAN_BLOCKS);
    scan_final_kernel<<<SCAN_BLOCKS, 1024>>>(cnt, bsums, rowptr, cursor, NN);
    fill_kernel<<<(EE + 255) / 256, 256>>>(erow, ecol, cursor, esrc, EE);
    zero_kernel<<<(BB * 256 + 255) / 256, 256>>>(x2, BB * 256);

    // layer 1: aggregate(x,64) -> gemm 64->128 +relu
    run_aggregate(x, dinv, rowptr, esrc, aggHi, aggLo, 64);
    run_gemm_mma(aggHi, aggLo, W1, b1, bufB, NN, 64, 128, 1);

    // layer 2: aggregate(h1,128) -> gemm 128->192 +relu
    run_aggregate(bufB, dinv, rowptr, esrc, aggHi, aggLo, 128);
    run_gemm_mma(aggHi, aggLo, W2, b2, bufB, NN, 128, 192, 1);

    // layer 3: aggregate(h2,192) -> gemm 192->256 +relu, fused segment-max pool
    run_aggregate(bufB, dinv, rowptr, esrc, aggHi, aggLo, 192);
    run_gemm_mma(aggHi, aggLo, W3, b3, bufB, NN, 192, 256, 1,
                 nullptr, nullptr, nullptr, batch, x2);

    // shared aggregation for mu / logvar heads
    run_aggregate(bufB, dinv, rowptr, esrc, aggHi, aggLo, 256);
    run_gemm_mma(aggHi, aggLo, Wmu, bmu, out_mu, NN, 256, 256, 0);
    run_gemm_mma(aggHi, aggLo, Wlv, blv, out_lv, NN, 256, 256, 0,
                 out_mu, eps, out_amvo);

    // MLP head on pooled features (tiny, fp32)
    {
        dim3 g1(1024 / 64, (BB + 127) / 128);
        sgemm_bias_kernel<<<g1, 256>>>(x2, fc1w, fc1b, hidden, BB, 256, 1024, 1);
        dim3 g2(128 / 64, (BB + 127) / 128);
        sgemm_bias_kernel<<<g2, 256>>>(hidden, fc2w, fc2b, out_pmvo, BB, 1024, 128, 0);
    }
}